// round 3
// baseline (speedup 1.0000x reference)
#include <cuda_runtime.h>
#include <math.h>

#define HEADS 8
#define HD 32
#define NPOS 2304
#define GW 48
#define CDIM 256
#define BATCH 2
#define MTOT (BATCH*NPOS)   // 4608

typedef unsigned long long ull;

// Scratch (static device arrays; no allocation allowed)
__device__ float g_q[BATCH*HEADS*NPOS*HD];     // [b][h][n][d] rotary-applied q
__device__ float g_k[BATCH*HEADS*NPOS*HD];     // [b][h][n][d] rotary-applied, scaled k
__device__ float g_v[BATCH*HEADS*NPOS*HD];     // [b][h][n][d] v
__device__ float g_lepe[BATCH*NPOS*CDIM];      // [b][n][c] depthwise conv out + bias
__device__ float g_attn[BATCH*NPOS*CDIM];      // [b][n][c] attention out (heads concat)
__device__ float g_wt[25*CDIM];                // transposed depthwise weights [tap][ch]

// ---- packed f32x2 helpers (Blackwell: 2x fp32 per issue slot) -------------
__device__ __forceinline__ ull f2fma(ull a, ull b, ull c) {
    ull d; asm("fma.rn.f32x2 %0, %1, %2, %3;" : "=l"(d) : "l"(a), "l"(b), "l"(c));
    return d;
}
__device__ __forceinline__ ull f2add(ull a, ull b) {
    ull d; asm("add.rn.f32x2 %0, %1, %2;" : "=l"(d) : "l"(a), "l"(b));
    return d;
}
__device__ __forceinline__ ull f2mul(ull a, ull b) {
    ull d; asm("mul.rn.f32x2 %0, %1, %2;" : "=l"(d) : "l"(a), "l"(b));
    return d;
}
__device__ __forceinline__ float2 f2unpack(ull a) {
    float2 f; asm("mov.b64 {%0, %1}, %2;" : "=f"(f.x), "=f"(f.y) : "l"(a));
    return f;
}
__device__ __forceinline__ ull f2pack(float x, float y) {
    ull d; asm("mov.b64 %0, {%1, %2};" : "=l"(d) : "f"(x), "f"(y));
    return d;
}

// ---------------------------------------------------------------------------
// Fused QKV GEMM: y = x @ W + b, with per-matrix epilogue
// ---------------------------------------------------------------------------
__global__ __launch_bounds__(256) void qkv_gemm(
    const float* __restrict__ x,
    const float* __restrict__ Wq, const float* __restrict__ bq,
    const float* __restrict__ Wk, const float* __restrict__ bk,
    const float* __restrict__ Wv, const float* __restrict__ bv)
{
    const int which = blockIdx.z;
    const float* __restrict__ W    = (which == 0) ? Wq : (which == 1 ? Wk : Wv);
    const float* __restrict__ bias = (which == 0) ? bq : (which == 1 ? bk : bv);

    __shared__ float As[16][64];
    __shared__ float Bs[16][64];

    const int tid = threadIdx.x;
    const int tx = tid & 15, ty = tid >> 4;
    const int mb = blockIdx.x * 64, nb = blockIdx.y * 64;

    float acc[4][4];
#pragma unroll
    for (int i = 0; i < 4; i++)
#pragma unroll
        for (int j = 0; j < 4; j++) acc[i][j] = 0.f;

    const int ar = tid >> 2, ac4 = (tid & 3) * 4;
    const int br = tid >> 4, bc4 = (tid & 15) * 4;

    for (int k0 = 0; k0 < CDIM; k0 += 16) {
        float4 a = *(const float4*)&x[(size_t)(mb + ar) * CDIM + k0 + ac4];
        As[ac4 + 0][ar] = a.x; As[ac4 + 1][ar] = a.y;
        As[ac4 + 2][ar] = a.z; As[ac4 + 3][ar] = a.w;
        *(float4*)&Bs[br][bc4] = *(const float4*)&W[(size_t)(k0 + br) * CDIM + nb + bc4];
        __syncthreads();
#pragma unroll
        for (int kk = 0; kk < 16; kk++) {
            float4 av = *(float4*)&As[kk][ty * 4];
            float4 bv4 = *(float4*)&Bs[kk][tx * 4];
            acc[0][0] += av.x * bv4.x; acc[0][1] += av.x * bv4.y;
            acc[0][2] += av.x * bv4.z; acc[0][3] += av.x * bv4.w;
            acc[1][0] += av.y * bv4.x; acc[1][1] += av.y * bv4.y;
            acc[1][2] += av.y * bv4.z; acc[1][3] += av.y * bv4.w;
            acc[2][0] += av.z * bv4.x; acc[2][1] += av.z * bv4.y;
            acc[2][2] += av.z * bv4.z; acc[2][3] += av.z * bv4.w;
            acc[3][0] += av.w * bv4.x; acc[3][1] += av.w * bv4.y;
            acc[3][2] += av.w * bv4.z; acc[3][3] += av.w * bv4.w;
        }
        __syncthreads();
    }

    const float scal = (which == 1) ? 0.17677669529663687f : 1.0f; // 32^-0.5

#pragma unroll
    for (int i = 0; i < 4; i++) {
        int row = mb + ty * 4 + i;
        int b = row / NPOS;
        int pos = row - b * NPOS;
        if (which == 2) {
#pragma unroll
            for (int j = 0; j < 4; j++) {
                int col = nb + tx * 4 + j;
                float val = acc[i][j] + bias[col];
                g_v[(((size_t)(b * HEADS + (col >> 5))) * NPOS + pos) * HD + (col & 31)] = val;
            }
        } else {
            float* dst = (which == 0) ? g_q : g_k;
#pragma unroll
            for (int jj = 0; jj < 4; jj += 2) {
                int col = nb + tx * 4 + jj;
                int d = col & 31;
                int pj = d >> 1;
                float ang = expf(-(float)pj * (9.210340371976184f / 15.0f));
                float s, c;
                sincosf((float)pos * ang, &s, &c);
                float v0 = (acc[i][jj] + bias[col]) * scal;
                float v1 = (acc[i][jj + 1] + bias[col + 1]) * scal;
                size_t base = (((size_t)(b * HEADS + (col >> 5))) * NPOS + pos) * HD + d;
                dst[base]     = v0 * c - v1 * s;
                dst[base + 1] = v1 * c + v0 * s;
            }
        }
    }
}

// ---------------------------------------------------------------------------
__global__ void transpose_w(const float* __restrict__ lw)
{
    int t = blockIdx.x * 256 + threadIdx.x;
    if (t < 25 * CDIM) {
        int ch = t / 25, tap = t - ch * 25;
        g_wt[tap * CDIM + ch] = lw[t];
    }
}

// ---------------------------------------------------------------------------
__global__ __launch_bounds__(256) void dwconv(const float* __restrict__ lepe_b)
{
    int t = blockIdx.x * 256 + threadIdx.x;
    int ch = t & 255;
    int sp = t >> 8;
    int b = sp / NPOS;
    int pos = sp - b * NPOS;
    int r = pos / GW, c = pos - (pos / GW) * GW;
    const float* vb = g_v + ((size_t)(b * HEADS + (ch >> 5)) * NPOS) * HD + (ch & 31);
    float sum = lepe_b[ch];
#pragma unroll
    for (int i = 0; i < 5; i++) {
        int rr = r + i - 2;
        if ((unsigned)rr < GW) {
#pragma unroll
            for (int j = 0; j < 5; j++) {
                int cc = c + j - 2;
                if ((unsigned)cc < GW) {
                    sum += vb[(size_t)(rr * GW + cc) * HD] * g_wt[(i * 5 + j) * CDIM + ch];
                }
            }
        }
    }
    g_lepe[t] = sum;
}

// ---------------------------------------------------------------------------
// Attention v2: 64 threads/block, 2 queries/thread (q0 = base+tid, q1 = q0+64).
// Packed f32x2 FMA for dot products and V accumulation. Flash-style 64-key
// SMEM tiles; logits bounded so no running max needed.
// grid = (18 q-tiles of 128, 16 bh), 64 threads.
// ---------------------------------------------------------------------------
__global__ __launch_bounds__(64) void attn_kernel()
{
    __shared__ float ks[64 * HD];
    __shared__ float vs[64 * HD];
    __shared__ float krf[64];
    __shared__ float kcf[64];

    const int bh = blockIdx.y;
    const int b = bh >> 3, h = bh & 7;
    const int tid = threadIdx.x;
    const int q0 = blockIdx.x * 128 + tid;
    const int q1 = q0 + 64;

    // Load both query rows as packed f32x2 pairs
    const ulonglong2* q0g = (const ulonglong2*)(g_q + ((size_t)bh * NPOS + q0) * HD);
    const ulonglong2* q1g = (const ulonglong2*)(g_q + ((size_t)bh * NPOS + q1) * HD);
    ull qp0[16], qp1[16];
#pragma unroll
    for (int i = 0; i < 8; i++) {
        ulonglong2 t0 = q0g[i]; qp0[2 * i] = t0.x; qp0[2 * i + 1] = t0.y;
        ulonglong2 t1 = q1g[i]; qp1[2 * i] = t1.x; qp1[2 * i + 1] = t1.y;
    }

    ull ap0[16], ap1[16];
#pragma unroll
    for (int i = 0; i < 16; i++) { ap0[i] = 0ull; ap1[i] = 0ull; }
    float l0 = 0.f, l1 = 0.f;

    const int qr0i = q0 / GW;
    const float qr0 = (float)qr0i, qc0 = (float)(q0 - qr0i * GW);
    const int qr1i = q1 / GW;
    const float qr1 = (float)qr1i, qc1 = (float)(q1 - qr1i * GW);
    const float decay = logf(1.0f - exp2f(-(1.0f + 0.375f * (float)h)));

    const float4* __restrict__ kglob = (const float4*)(g_k + (size_t)bh * NPOS * HD);
    const float4* __restrict__ vglob = (const float4*)(g_v + (size_t)bh * NPOS * HD);

    for (int t = 0; t < NPOS / 64; t++) {
        __syncthreads();
#pragma unroll
        for (int i = 0; i < 8; i++) {
            int idx = tid + i * 64;                 // 0..511 float4s
            ((float4*)ks)[idx] = kglob[t * 512 + idx];
            ((float4*)vs)[idx] = vglob[t * 512 + idx];
        }
        {
            int kk = t * 64 + tid;
            int kr = kk / GW;
            krf[tid] = (float)kr;
            kcf[tid] = (float)(kk - kr * GW);
        }
        __syncthreads();

        for (int j = 0; j < 64; j++) {
            const ulonglong2* kj = (const ulonglong2*)(ks + j * HD);
            ull d0a = 0ull, d0b = 0ull, d1a = 0ull, d1b = 0ull;
#pragma unroll
            for (int i = 0; i < 8; i++) {
                ulonglong2 kv = kj[i];
                d0a = f2fma(qp0[2 * i],     kv.x, d0a);
                d0b = f2fma(qp0[2 * i + 1], kv.y, d0b);
                d1a = f2fma(qp1[2 * i],     kv.x, d1a);
                d1b = f2fma(qp1[2 * i + 1], kv.y, d1b);
            }
            float2 s0 = f2unpack(f2add(d0a, d0b));
            float2 s1 = f2unpack(f2add(d1a, d1b));
            float dot0 = s0.x + s0.y;
            float dot1 = s1.x + s1.y;

            float kr = krf[j], kc = kcf[j];
            float arg0 = fmaf(decay, fabsf(qr0 - kr) + fabsf(qc0 - kc), dot0);
            float arg1 = fmaf(decay, fabsf(qr1 - kr) + fabsf(qc1 - kc), dot1);
            float p0 = __expf(arg0); l0 += p0;
            float p1 = __expf(arg1); l1 += p1;
            ull pp0 = f2pack(p0, p0);
            ull pp1 = f2pack(p1, p1);

            const ulonglong2* vj = (const ulonglong2*)(vs + j * HD);
#pragma unroll
            for (int i = 0; i < 8; i++) {
                ulonglong2 vv = vj[i];
                ap0[2 * i]     = f2fma(pp0, vv.x, ap0[2 * i]);
                ap0[2 * i + 1] = f2fma(pp0, vv.y, ap0[2 * i + 1]);
                ap1[2 * i]     = f2fma(pp1, vv.x, ap1[2 * i]);
                ap1[2 * i + 1] = f2fma(pp1, vv.y, ap1[2 * i + 1]);
            }
        }
    }

    const float inv0 = 1.0f / l0;
    const float inv1 = 1.0f / l1;
    const ull iv0 = f2pack(inv0, inv0);
    const ull iv1 = f2pack(inv1, inv1);
    ull* o0 = (ull*)(g_attn + ((size_t)(b * NPOS + q0)) * CDIM + h * HD);
    ull* o1 = (ull*)(g_attn + ((size_t)(b * NPOS + q1)) * CDIM + h * HD);
#pragma unroll
    for (int i = 0; i < 16; i++) o0[i] = f2mul(ap0[i], iv0);
#pragma unroll
    for (int i = 0; i < 16; i++) o1[i] = f2mul(ap1[i], iv1);
}

// ---------------------------------------------------------------------------
// Output GEMM: out = (g_attn + g_lepe) @ Wo + bo
// ---------------------------------------------------------------------------
__global__ __launch_bounds__(256) void out_gemm(
    const float* __restrict__ Wo, const float* __restrict__ bo,
    float* __restrict__ out)
{
    __shared__ float As[16][64];
    __shared__ float Bs[16][64];

    const int tid = threadIdx.x;
    const int tx = tid & 15, ty = tid >> 4;
    const int mb = blockIdx.x * 64, nb = blockIdx.y * 64;

    float acc[4][4];
#pragma unroll
    for (int i = 0; i < 4; i++)
#pragma unroll
        for (int j = 0; j < 4; j++) acc[i][j] = 0.f;

    const int ar = tid >> 2, ac4 = (tid & 3) * 4;
    const int br = tid >> 4, bc4 = (tid & 15) * 4;

    for (int k0 = 0; k0 < CDIM; k0 += 16) {
        size_t aoff = (size_t)(mb + ar) * CDIM + k0 + ac4;
        float4 a1 = *(const float4*)&g_attn[aoff];
        float4 a2 = *(const float4*)&g_lepe[aoff];
        As[ac4 + 0][ar] = a1.x + a2.x; As[ac4 + 1][ar] = a1.y + a2.y;
        As[ac4 + 2][ar] = a1.z + a2.z; As[ac4 + 3][ar] = a1.w + a2.w;
        *(float4*)&Bs[br][bc4] = *(const float4*)&Wo[(size_t)(k0 + br) * CDIM + nb + bc4];
        __syncthreads();
#pragma unroll
        for (int kk = 0; kk < 16; kk++) {
            float4 av = *(float4*)&As[kk][ty * 4];
            float4 bv4 = *(float4*)&Bs[kk][tx * 4];
            acc[0][0] += av.x * bv4.x; acc[0][1] += av.x * bv4.y;
            acc[0][2] += av.x * bv4.z; acc[0][3] += av.x * bv4.w;
            acc[1][0] += av.y * bv4.x; acc[1][1] += av.y * bv4.y;
            acc[1][2] += av.y * bv4.z; acc[1][3] += av.y * bv4.w;
            acc[2][0] += av.z * bv4.x; acc[2][1] += av.z * bv4.y;
            acc[2][2] += av.z * bv4.z; acc[2][3] += av.z * bv4.w;
            acc[3][0] += av.w * bv4.x; acc[3][1] += av.w * bv4.y;
            acc[3][2] += av.w * bv4.z; acc[3][3] += av.w * bv4.w;
        }
        __syncthreads();
    }

#pragma unroll
    for (int i = 0; i < 4; i++) {
        int row = mb + ty * 4 + i;
#pragma unroll
        for (int j = 0; j < 4; j++) {
            int col = nb + tx * 4 + j;
            out[(size_t)row * CDIM + col] = acc[i][j] + bo[col];
        }
    }
}

// ---------------------------------------------------------------------------
extern "C" void kernel_launch(void* const* d_in, const int* in_sizes, int n_in,
                              void* d_out, int out_size)
{
    const float* x      = (const float*)d_in[0];
    const float* Wq     = (const float*)d_in[1];
    const float* bq     = (const float*)d_in[2];
    const float* Wk     = (const float*)d_in[3];
    const float* bk     = (const float*)d_in[4];
    const float* Wv     = (const float*)d_in[5];
    const float* bv     = (const float*)d_in[6];
    const float* lepe_w = (const float*)d_in[7];
    const float* lepe_b = (const float*)d_in[8];
    const float* Wo     = (const float*)d_in[9];
    const float* bo     = (const float*)d_in[10];
    float* out = (float*)d_out;

    dim3 g1(MTOT / 64, CDIM / 64, 3);
    qkv_gemm<<<g1, 256>>>(x, Wq, bq, Wk, bk, Wv, bv);

    transpose_w<<<(25 * CDIM + 255) / 256, 256>>>(lepe_w);

    dwconv<<<MTOT, 256>>>(lepe_b);

    dim3 g3(NPOS / 128, BATCH * HEADS);
    attn_kernel<<<g3, 64>>>();

    dim3 g4(MTOT / 64, CDIM / 64);
    out_gemm<<<g4, 256>>>(Wo, bo, out);
}

// round 5
// speedup vs baseline: 1.9744x; 1.9744x over previous
#include <cuda_runtime.h>
#include <math.h>

#define HEADS 8
#define HD 32
#define NPOS 2304
#define GW 48
#define CDIM 256
#define BATCH 2
#define MTOT (BATCH*NPOS)   // 4608
#define BH (BATCH*HEADS)    // 16

typedef unsigned long long ull;

// Scratch (static device arrays; no allocation allowed)
__device__ float g_q[BATCH*HEADS*NPOS*HD];
__device__ float g_k[BATCH*HEADS*NPOS*HD];
__device__ float g_v[BATCH*HEADS*NPOS*HD];
__device__ float g_lepe[BATCH*NPOS*CDIM];
__device__ float g_attn[BATCH*NPOS*CDIM];
__device__ float g_wt[25*CDIM];
__device__ float g_sin[NPOS*16];
__device__ float g_cos[NPOS*16];
// split-K partials: [half][bh][q][HD] and [half][bh][q]
__device__ float g_part[2*BH*NPOS*HD];
__device__ float g_partl[2*BH*NPOS];

// ---- packed f32x2 helpers --------------------------------------------------
__device__ __forceinline__ ull f2fma(ull a, ull b, ull c) {
    ull d; asm("fma.rn.f32x2 %0, %1, %2, %3;" : "=l"(d) : "l"(a), "l"(b), "l"(c));
    return d;
}
__device__ __forceinline__ ull f2add(ull a, ull b) {
    ull d; asm("add.rn.f32x2 %0, %1, %2;" : "=l"(d) : "l"(a), "l"(b));
    return d;
}
__device__ __forceinline__ float2 f2unpack(ull a) {
    float2 f; asm("mov.b64 {%0, %1}, %2;" : "=f"(f.x), "=f"(f.y) : "l"(a));
    return f;
}
__device__ __forceinline__ ull f2pack(float x, float y) {
    ull d; asm("mov.b64 %0, {%1, %2};" : "=l"(d) : "f"(x), "f"(y));
    return d;
}

// ---------------------------------------------------------------------------
// Precompute rotary sin/cos table: pos in [0,NPOS), pair pj in [0,16)
// ---------------------------------------------------------------------------
__global__ void rotary_table()
{
    int t = blockIdx.x * 256 + threadIdx.x;   // NPOS*16 = 36864
    if (t < NPOS * 16) {
        int pos = t >> 4, pj = t & 15;
        float ang = expf(-(float)pj * (9.210340371976184f / 15.0f));
        float s, c;
        sincosf((float)pos * ang, &s, &c);
        g_sin[t] = s;
        g_cos[t] = c;
    }
}

// ---------------------------------------------------------------------------
// Fused QKV GEMM: y = x @ W + b, with per-matrix epilogue
// ---------------------------------------------------------------------------
__global__ __launch_bounds__(256) void qkv_gemm(
    const float* __restrict__ x,
    const float* __restrict__ Wq, const float* __restrict__ bq,
    const float* __restrict__ Wk, const float* __restrict__ bk,
    const float* __restrict__ Wv, const float* __restrict__ bv)
{
    const int which = blockIdx.z;
    const float* __restrict__ W    = (which == 0) ? Wq : (which == 1 ? Wk : Wv);
    const float* __restrict__ bias = (which == 0) ? bq : (which == 1 ? bk : bv);

    __shared__ float As[16][64];
    __shared__ float Bs[16][64];

    const int tid = threadIdx.x;
    const int tx = tid & 15, ty = tid >> 4;
    const int mb = blockIdx.x * 64, nb = blockIdx.y * 64;

    float acc[4][4];
#pragma unroll
    for (int i = 0; i < 4; i++)
#pragma unroll
        for (int j = 0; j < 4; j++) acc[i][j] = 0.f;

    const int ar = tid >> 2, ac4 = (tid & 3) * 4;
    const int br = tid >> 4, bc4 = (tid & 15) * 4;

    for (int k0 = 0; k0 < CDIM; k0 += 16) {
        float4 a = *(const float4*)&x[(size_t)(mb + ar) * CDIM + k0 + ac4];
        As[ac4 + 0][ar] = a.x; As[ac4 + 1][ar] = a.y;
        As[ac4 + 2][ar] = a.z; As[ac4 + 3][ar] = a.w;
        *(float4*)&Bs[br][bc4] = *(const float4*)&W[(size_t)(k0 + br) * CDIM + nb + bc4];
        __syncthreads();
#pragma unroll
        for (int kk = 0; kk < 16; kk++) {
            float4 av = *(float4*)&As[kk][ty * 4];
            float4 bv4 = *(float4*)&Bs[kk][tx * 4];
            acc[0][0] += av.x * bv4.x; acc[0][1] += av.x * bv4.y;
            acc[0][2] += av.x * bv4.z; acc[0][3] += av.x * bv4.w;
            acc[1][0] += av.y * bv4.x; acc[1][1] += av.y * bv4.y;
            acc[1][2] += av.y * bv4.z; acc[1][3] += av.y * bv4.w;
            acc[2][0] += av.z * bv4.x; acc[2][1] += av.z * bv4.y;
            acc[2][2] += av.z * bv4.z; acc[2][3] += av.z * bv4.w;
            acc[3][0] += av.w * bv4.x; acc[3][1] += av.w * bv4.y;
            acc[3][2] += av.w * bv4.z; acc[3][3] += av.w * bv4.w;
        }
        __syncthreads();
    }

    const float scal = (which == 1) ? 0.17677669529663687f : 1.0f;

#pragma unroll
    for (int i = 0; i < 4; i++) {
        int row = mb + ty * 4 + i;
        int b = row / NPOS;
        int pos = row - b * NPOS;
        if (which == 2) {
#pragma unroll
            for (int j = 0; j < 4; j++) {
                int col = nb + tx * 4 + j;
                float val = acc[i][j] + bias[col];
                g_v[(((size_t)(b * HEADS + (col >> 5))) * NPOS + pos) * HD + (col & 31)] = val;
            }
        } else {
            float* dst = (which == 0) ? g_q : g_k;
#pragma unroll
            for (int jj = 0; jj < 4; jj += 2) {
                int col = nb + tx * 4 + jj;
                int d = col & 31;
                int pj = d >> 1;
                float s = g_sin[pos * 16 + pj];
                float c = g_cos[pos * 16 + pj];
                float v0 = (acc[i][jj] + bias[col]) * scal;
                float v1 = (acc[i][jj + 1] + bias[col + 1]) * scal;
                size_t base = (((size_t)(b * HEADS + (col >> 5))) * NPOS + pos) * HD + d;
                dst[base]     = v0 * c - v1 * s;
                dst[base + 1] = v1 * c + v0 * s;
            }
        }
    }
}

// ---------------------------------------------------------------------------
__global__ void transpose_w(const float* __restrict__ lw)
{
    int t = blockIdx.x * 256 + threadIdx.x;
    if (t < 25 * CDIM) {
        int ch = t / 25, tap = t - ch * 25;
        g_wt[tap * CDIM + ch] = lw[t];
    }
}

// ---------------------------------------------------------------------------
__global__ __launch_bounds__(256) void dwconv(const float* __restrict__ lepe_b)
{
    int t = blockIdx.x * 256 + threadIdx.x;
    int ch = t & 255;
    int sp = t >> 8;
    int b = sp / NPOS;
    int pos = sp - b * NPOS;
    int r = pos / GW, c = pos - (pos / GW) * GW;
    const float* vb = g_v + ((size_t)(b * HEADS + (ch >> 5)) * NPOS) * HD + (ch & 31);
    float sum = lepe_b[ch];
#pragma unroll
    for (int i = 0; i < 5; i++) {
        int rr = r + i - 2;
        if ((unsigned)rr < GW) {
#pragma unroll
            for (int j = 0; j < 5; j++) {
                int cc = c + j - 2;
                if ((unsigned)cc < GW) {
                    sum += vb[(size_t)(rr * GW + cc) * HD] * g_wt[(i * 5 + j) * CDIM + ch];
                }
            }
        }
    }
    g_lepe[t] = sum;
}

// ---------------------------------------------------------------------------
// Attention v3: 1 query/thread, 128 threads, f32x2 FMA, split-K over 2 halves.
// grid = (18 q-tiles, 16 bh, 2 halves). Partials (acc, l) -> merge kernel.
// ---------------------------------------------------------------------------
__global__ __launch_bounds__(128) void attn_kernel()
{
    __shared__ float ks[64 * HD];
    __shared__ float vs[64 * HD];
    __shared__ float krf[64];
    __shared__ float kcf[64];

    const int bh = blockIdx.y;
    const int h = bh & 7;
    const int half = blockIdx.z;
    const int tid = threadIdx.x;
    const int qidx = blockIdx.x * 128 + tid;

    const ulonglong2* qg = (const ulonglong2*)(g_q + ((size_t)bh * NPOS + qidx) * HD);
    ull qp[16];
#pragma unroll
    for (int i = 0; i < 8; i++) {
        ulonglong2 t0 = qg[i]; qp[2 * i] = t0.x; qp[2 * i + 1] = t0.y;
    }

    ull ap[16];
#pragma unroll
    for (int i = 0; i < 16; i++) ap[i] = 0ull;
    float l = 0.f;

    const int qri = qidx / GW;
    const float qr = (float)qri, qc = (float)(qidx - qri * GW);
    const float decay = logf(1.0f - exp2f(-(1.0f + 0.375f * (float)h)));

    const int k0base = half * (NPOS / 2);
    const float4* __restrict__ kglob = (const float4*)(g_k + ((size_t)bh * NPOS + k0base) * HD);
    const float4* __restrict__ vglob = (const float4*)(g_v + ((size_t)bh * NPOS + k0base) * HD);

    for (int t = 0; t < NPOS / 128; t++) {     // 18 tiles of 64 keys
        __syncthreads();
#pragma unroll
        for (int i = 0; i < 4; i++) {
            int idx = tid + i * 128;           // 0..511 float4s
            ((float4*)ks)[idx] = kglob[t * 512 + idx];
            ((float4*)vs)[idx] = vglob[t * 512 + idx];
        }
        if (tid < 64) {
            int kk = k0base + t * 64 + tid;
            int kr = kk / GW;
            krf[tid] = (float)kr;
            kcf[tid] = (float)(kk - kr * GW);
        }
        __syncthreads();

#pragma unroll 2
        for (int j = 0; j < 64; j++) {
            const ulonglong2* kj = (const ulonglong2*)(ks + j * HD);
            ull d0 = 0ull, d1 = 0ull, d2 = 0ull, d3 = 0ull;
#pragma unroll
            for (int i = 0; i < 4; i++) {
                ulonglong2 ka = kj[2 * i];
                ulonglong2 kb = kj[2 * i + 1];
                d0 = f2fma(qp[4 * i + 0], ka.x, d0);
                d1 = f2fma(qp[4 * i + 1], ka.y, d1);
                d2 = f2fma(qp[4 * i + 2], kb.x, d2);
                d3 = f2fma(qp[4 * i + 3], kb.y, d3);
            }
            float2 s = f2unpack(f2add(f2add(d0, d1), f2add(d2, d3)));
            float dot = s.x + s.y;

            float dist = fabsf(qr - krf[j]) + fabsf(qc - kcf[j]);
            float p = __expf(fmaf(decay, dist, dot));
            l += p;
            ull pp = f2pack(p, p);

            const ulonglong2* vj = (const ulonglong2*)(vs + j * HD);
#pragma unroll
            for (int i = 0; i < 8; i++) {
                ulonglong2 vv = vj[i];
                ap[2 * i]     = f2fma(pp, vv.x, ap[2 * i]);
                ap[2 * i + 1] = f2fma(pp, vv.y, ap[2 * i + 1]);
            }
        }
    }

    ull* pa = (ull*)(g_part + (((size_t)half * BH + bh) * NPOS + qidx) * HD);
#pragma unroll
    for (int i = 0; i < 16; i++) pa[i] = ap[i];
    g_partl[(half * BH + bh) * NPOS + qidx] = l;
}

// ---------------------------------------------------------------------------
// Merge split-K halves: g_attn[b][q][h*HD..] = (a0+a1)/(l0+l1)
// ---------------------------------------------------------------------------
__global__ __launch_bounds__(256) void attn_merge()
{
    int t = blockIdx.x * 256 + threadIdx.x;   // BH*NPOS = 36864
    if (t >= BH * NPOS) return;
    int bh = t / NPOS;
    int q = t - bh * NPOS;
    int b = bh >> 3, h = bh & 7;

    float l0 = g_partl[bh * NPOS + q];
    float l1 = g_partl[(BH + bh) * NPOS + q];
    float inv = 1.0f / (l0 + l1);

    const float4* a0 = (const float4*)(g_part + (((size_t)bh) * NPOS + q) * HD);
    const float4* a1 = (const float4*)(g_part + (((size_t)BH + bh) * NPOS + q) * HD);
    float4* o = (float4*)(g_attn + ((size_t)(b * NPOS + q)) * CDIM + h * HD);
#pragma unroll
    for (int i = 0; i < 8; i++) {
        float4 x0 = a0[i], x1 = a1[i];
        o[i] = make_float4((x0.x + x1.x) * inv, (x0.y + x1.y) * inv,
                           (x0.z + x1.z) * inv, (x0.w + x1.w) * inv);
    }
}

// ---------------------------------------------------------------------------
// Output GEMM: out = (g_attn + g_lepe) @ Wo + bo
// ---------------------------------------------------------------------------
__global__ __launch_bounds__(256) void out_gemm(
    const float* __restrict__ Wo, const float* __restrict__ bo,
    float* __restrict__ out)
{
    __shared__ float As[16][64];
    __shared__ float Bs[16][64];

    const int tid = threadIdx.x;
    const int tx = tid & 15, ty = tid >> 4;
    const int mb = blockIdx.x * 64, nb = blockIdx.y * 64;

    float acc[4][4];
#pragma unroll
    for (int i = 0; i < 4; i++)
#pragma unroll
        for (int j = 0; j < 4; j++) acc[i][j] = 0.f;

    const int ar = tid >> 2, ac4 = (tid & 3) * 4;
    const int br = tid >> 4, bc4 = (tid & 15) * 4;

    for (int k0 = 0; k0 < CDIM; k0 += 16) {
        size_t aoff = (size_t)(mb + ar) * CDIM + k0 + ac4;
        float4 a1 = *(const float4*)&g_attn[aoff];
        float4 a2 = *(const float4*)&g_lepe[aoff];
        As[ac4 + 0][ar] = a1.x + a2.x; As[ac4 + 1][ar] = a1.y + a2.y;
        As[ac4 + 2][ar] = a1.z + a2.z; As[ac4 + 3][ar] = a1.w + a2.w;
        *(float4*)&Bs[br][bc4] = *(const float4*)&Wo[(size_t)(k0 + br) * CDIM + nb + bc4];
        __syncthreads();
#pragma unroll
        for (int kk = 0; kk < 16; kk++) {
            float4 av = *(float4*)&As[kk][ty * 4];
            float4 bv4 = *(float4*)&Bs[kk][tx * 4];
            acc[0][0] += av.x * bv4.x; acc[0][1] += av.x * bv4.y;
            acc[0][2] += av.x * bv4.z; acc[0][3] += av.x * bv4.w;
            acc[1][0] += av.y * bv4.x; acc[1][1] += av.y * bv4.y;
            acc[1][2] += av.y * bv4.z; acc[1][3] += av.y * bv4.w;
            acc[2][0] += av.z * bv4.x; acc[2][1] += av.z * bv4.y;
            acc[2][2] += av.z * bv4.z; acc[2][3] += av.z * bv4.w;
            acc[3][0] += av.w * bv4.x; acc[3][1] += av.w * bv4.y;
            acc[3][2] += av.w * bv4.z; acc[3][3] += av.w * bv4.w;
        }
        __syncthreads();
    }

#pragma unroll
    for (int i = 0; i < 4; i++) {
        int row = mb + ty * 4 + i;
#pragma unroll
        for (int j = 0; j < 4; j++) {
            int col = nb + tx * 4 + j;
            out[(size_t)row * CDIM + col] = acc[i][j] + bo[col];
        }
    }
}

// ---------------------------------------------------------------------------
extern "C" void kernel_launch(void* const* d_in, const int* in_sizes, int n_in,
                              void* d_out, int out_size)
{
    const float* x      = (const float*)d_in[0];
    const float* Wq     = (const float*)d_in[1];
    const float* bq     = (const float*)d_in[2];
    const float* Wk     = (const float*)d_in[3];
    const float* bk     = (const float*)d_in[4];
    const float* Wv     = (const float*)d_in[5];
    const float* bv     = (const float*)d_in[6];
    const float* lepe_w = (const float*)d_in[7];
    const float* lepe_b = (const float*)d_in[8];
    const float* Wo     = (const float*)d_in[9];
    const float* bo     = (const float*)d_in[10];
    float* out = (float*)d_out;

    rotary_table<<<(NPOS * 16 + 255) / 256, 256>>>();
    transpose_w<<<(25 * CDIM + 255) / 256, 256>>>(lepe_w);

    dim3 g1(MTOT / 64, CDIM / 64, 3);
    qkv_gemm<<<g1, 256>>>(x, Wq, bq, Wk, bk, Wv, bv);

    dwconv<<<MTOT, 256>>>(lepe_b);

    dim3 g3(NPOS / 128, BH, 2);
    attn_kernel<<<g3, 128>>>();

    attn_merge<<<(BH * NPOS + 255) / 256, 256>>>();

    dim3 g4(MTOT / 64, CDIM / 64);
    out_gemm<<<g4, 256>>>(Wo, bo, out);
}

// round 10
// speedup vs baseline: 3.2552x; 1.6487x over previous
#include <cuda_runtime.h>
#include <cuda_bf16.h>
#include <math.h>
#include <cstdint>

#define HEADS 8
#define HD 32
#define NPOS 2304
#define GW 48
#define CDIM 256
#define BATCH 2
#define MTOT (BATCH*NPOS)   // 4608
#define BH (BATCH*HEADS)    // 16

// Scratch (static device arrays; no allocation allowed)
__device__ float g_v[BATCH*HEADS*NPOS*HD];    // [bh][n][d] fp32 full precision (dwconv, vt source)
__device__ float g_q[BATCH*HEADS*NPOS*HD];    // [bh][n][d] rotary q, tf32-rounded
__device__ float g_k[BATCH*HEADS*NPOS*HD];    // [bh][n][d] rotary scaled k, tf32-rounded
__device__ float g_vt[BATCH*HEADS*HD*NPOS];   // [bh][d][n] V transposed, tf32-rounded
__device__ float g_lepe[BATCH*NPOS*CDIM];
__device__ float g_attn[BATCH*NPOS*CDIM];
__device__ float g_wt[25*CDIM];
__device__ float g_sin[NPOS*16];
__device__ float g_cos[NPOS*16];

// ---- tf32 helpers ----------------------------------------------------------
__device__ __forceinline__ uint32_t to_tf32(float f)
{
    uint32_t r;
    asm("cvt.rna.tf32.f32 %0, %1;" : "=r"(r) : "f"(f));
    return r;
}
__device__ __forceinline__ float to_tf32f(float f)
{
    return __uint_as_float(to_tf32(f));
}
// mma.sync m16n8k8 tf32 (baseline sm_80 PTX)
__device__ __forceinline__ void mma_tf32(
    float* d, const uint32_t* a, uint32_t b0, uint32_t b1, const float* c)
{
    asm volatile(
        "mma.sync.aligned.m16n8k8.row.col.f32.tf32.tf32.f32 "
        "{%0,%1,%2,%3}, {%4,%5,%6,%7}, {%8,%9}, {%10,%11,%12,%13};"
        : "=f"(d[0]), "=f"(d[1]), "=f"(d[2]), "=f"(d[3])
        : "r"(a[0]), "r"(a[1]), "r"(a[2]), "r"(a[3]),
          "r"(b0), "r"(b1),
          "f"(c[0]), "f"(c[1]), "f"(c[2]), "f"(c[3]));
}

// ---------------------------------------------------------------------------
__global__ void rotary_table()
{
    int t = blockIdx.x * 256 + threadIdx.x;
    if (t < NPOS * 16) {
        int pos = t >> 4, pj = t & 15;
        float ang = expf(-(float)pj * (9.210340371976184f / 15.0f));
        float s, c;
        sincosf((float)pos * ang, &s, &c);
        g_sin[t] = s;
        g_cos[t] = c;
    }
}

// ---------------------------------------------------------------------------
// Fused QKV GEMM: y = x @ W + b; epilogues: q/k rotary + tf32 rounding, v fp32
// ---------------------------------------------------------------------------
__global__ __launch_bounds__(256) void qkv_gemm(
    const float* __restrict__ x,
    const float* __restrict__ Wq, const float* __restrict__ bq,
    const float* __restrict__ Wk, const float* __restrict__ bk,
    const float* __restrict__ Wv, const float* __restrict__ bv)
{
    const int which = blockIdx.z;
    const float* __restrict__ W    = (which == 0) ? Wq : (which == 1 ? Wk : Wv);
    const float* __restrict__ bias = (which == 0) ? bq : (which == 1 ? bk : bv);

    __shared__ float As[16][64];
    __shared__ float Bs[16][64];

    const int tid = threadIdx.x;
    const int tx = tid & 15, ty = tid >> 4;
    const int mb = blockIdx.x * 64, nb = blockIdx.y * 64;

    float acc[4][4];
#pragma unroll
    for (int i = 0; i < 4; i++)
#pragma unroll
        for (int j = 0; j < 4; j++) acc[i][j] = 0.f;

    const int ar = tid >> 2, ac4 = (tid & 3) * 4;
    const int br = tid >> 4, bc4 = (tid & 15) * 4;

    for (int k0 = 0; k0 < CDIM; k0 += 16) {
        float4 a = *(const float4*)&x[(size_t)(mb + ar) * CDIM + k0 + ac4];
        As[ac4 + 0][ar] = a.x; As[ac4 + 1][ar] = a.y;
        As[ac4 + 2][ar] = a.z; As[ac4 + 3][ar] = a.w;
        *(float4*)&Bs[br][bc4] = *(const float4*)&W[(size_t)(k0 + br) * CDIM + nb + bc4];
        __syncthreads();
#pragma unroll
        for (int kk = 0; kk < 16; kk++) {
            float4 av = *(float4*)&As[kk][ty * 4];
            float4 bv4 = *(float4*)&Bs[kk][tx * 4];
            acc[0][0] += av.x * bv4.x; acc[0][1] += av.x * bv4.y;
            acc[0][2] += av.x * bv4.z; acc[0][3] += av.x * bv4.w;
            acc[1][0] += av.y * bv4.x; acc[1][1] += av.y * bv4.y;
            acc[1][2] += av.y * bv4.z; acc[1][3] += av.y * bv4.w;
            acc[2][0] += av.z * bv4.x; acc[2][1] += av.z * bv4.y;
            acc[2][2] += av.z * bv4.z; acc[2][3] += av.z * bv4.w;
            acc[3][0] += av.w * bv4.x; acc[3][1] += av.w * bv4.y;
            acc[3][2] += av.w * bv4.z; acc[3][3] += av.w * bv4.w;
        }
        __syncthreads();
    }

    const float scal = (which == 1) ? 0.17677669529663687f : 1.0f;

#pragma unroll
    for (int i = 0; i < 4; i++) {
        int row = mb + ty * 4 + i;
        int b = row / NPOS;
        int pos = row - b * NPOS;
        if (which == 2) {
#pragma unroll
            for (int j = 0; j < 4; j++) {
                int col = nb + tx * 4 + j;
                float val = acc[i][j] + bias[col];
                g_v[(((size_t)(b * HEADS + (col >> 5))) * NPOS + pos) * HD + (col & 31)] = val;
            }
        } else {
            float* dst = (which == 0) ? g_q : g_k;
#pragma unroll
            for (int jj = 0; jj < 4; jj += 2) {
                int col = nb + tx * 4 + jj;
                int d = col & 31;
                int pj = d >> 1;
                float s = g_sin[pos * 16 + pj];
                float c = g_cos[pos * 16 + pj];
                float v0 = (acc[i][jj] + bias[col]) * scal;
                float v1 = (acc[i][jj + 1] + bias[col + 1]) * scal;
                size_t base = (((size_t)(b * HEADS + (col >> 5))) * NPOS + pos) * HD + d;
                dst[base]     = to_tf32f(v0 * c - v1 * s);
                dst[base + 1] = to_tf32f(v1 * c + v0 * s);
            }
        }
    }
}

// ---------------------------------------------------------------------------
// Transpose V: [bh][n][d] fp32 -> [bh][d][n] tf32-rounded fp32
// grid (NPOS/32, BH), block (32, 8)
// ---------------------------------------------------------------------------
__global__ __launch_bounds__(256) void vt_kernel()
{
    __shared__ float tile[32][33];
    const int bh = blockIdx.y;
    const int p0 = blockIdx.x * 32;
    const int tx = threadIdx.x, ty = threadIdx.y;
#pragma unroll
    for (int i = 0; i < 4; i++) {
        int row = ty + i * 8;
        tile[row][tx] = g_v[((size_t)bh * NPOS + p0 + row) * HD + tx];
    }
    __syncthreads();
#pragma unroll
    for (int i = 0; i < 4; i++) {
        int d = ty + i * 8;
        g_vt[((size_t)bh * HD + d) * NPOS + p0 + tx] = to_tf32f(tile[tx][d]);
    }
}

// ---------------------------------------------------------------------------
__global__ void transpose_w(const float* __restrict__ lw)
{
    int t = blockIdx.x * 256 + threadIdx.x;
    if (t < 25 * CDIM) {
        int ch = t / 25, tap = t - ch * 25;
        g_wt[tap * CDIM + ch] = lw[t];
    }
}

// ---------------------------------------------------------------------------
__global__ __launch_bounds__(256) void dwconv(const float* __restrict__ lepe_b)
{
    int t = blockIdx.x * 256 + threadIdx.x;
    int ch = t & 255;
    int sp = t >> 8;
    int b = sp / NPOS;
    int pos = sp - b * NPOS;
    int r = pos / GW, c = pos - (pos / GW) * GW;
    const float* vb = g_v + ((size_t)(b * HEADS + (ch >> 5)) * NPOS) * HD + (ch & 31);
    float sum = lepe_b[ch];
#pragma unroll
    for (int i = 0; i < 5; i++) {
        int rr = r + i - 2;
        if ((unsigned)rr < GW) {
#pragma unroll
            for (int j = 0; j < 5; j++) {
                int cc = c + j - 2;
                if ((unsigned)cc < GW) {
                    sum += vb[(size_t)(rr * GW + cc) * HD] * g_wt[(i * 5 + j) * CDIM + ch];
                }
            }
        }
    }
    g_lepe[t] = sum;
}

// ---------------------------------------------------------------------------
// Flash attention via mma.sync tf32 m16n8k8. grid (NPOS/64, BH), block 128.
// Each warp owns 16 query rows. K/V tiles of 128 keys in SMEM.
// K rows padded to 36 floats (144B): frag-load bank = 4*grp+t4, conflict-free.
// VT rows padded to 132 floats (528B): same property.
// ---------------------------------------------------------------------------
#define KS_F 36
#define VT_F 132

__global__ __launch_bounds__(128) void attn_mma()
{
    __shared__ __align__(16) float ksS[128 * KS_F];   // 18432 B
    __shared__ __align__(16) float vtS[32 * VT_F];    // 16896 B
    __shared__ float krf[128], kcf[128];

    const int tid = threadIdx.x;
    const int lane = tid & 31, wid = tid >> 5;
    const int grp = lane >> 2, t4 = lane & 3;
    const int bh = blockIdx.y, h = bh & 7, b = bh >> 3;
    const int q0 = blockIdx.x * 64;
    const int qrow0 = q0 + wid * 16 + grp;
    const int qrow1 = qrow0 + 8;

    // Q fragments: 4 k-steps (k8), 4 regs each (values already tf32-rounded)
    uint32_t qA[4][4];
    {
        const float* qb = g_q + (size_t)bh * NPOS * HD;
#pragma unroll
        for (int s = 0; s < 4; s++) {
            qA[s][0] = __float_as_uint(qb[(size_t)qrow0 * HD + s * 8 + t4]);
            qA[s][1] = __float_as_uint(qb[(size_t)qrow1 * HD + s * 8 + t4]);
            qA[s][2] = __float_as_uint(qb[(size_t)qrow0 * HD + s * 8 + t4 + 4]);
            qA[s][3] = __float_as_uint(qb[(size_t)qrow1 * HD + s * 8 + t4 + 4]);
        }
    }

    float o[4][4];
#pragma unroll
    for (int i = 0; i < 4; i++)
#pragma unroll
        for (int j = 0; j < 4; j++) o[i][j] = 0.f;
    float l0 = 0.f, l1 = 0.f;

    const int qr0i = qrow0 / GW;
    const float qr0 = (float)qr0i, qc0 = (float)(qrow0 - qr0i * GW);
    const int qr1i = qrow1 / GW;
    const float qr1 = (float)qr1i, qc1 = (float)(qrow1 - qr1i * GW);
    const float decay = logf(1.0f - exp2f(-(1.0f + 0.375f * (float)h)));

    const float* kb = g_k + (size_t)bh * NPOS * HD;
    const float* vtb = g_vt + (size_t)bh * HD * NPOS;

    for (int t = 0; t < NPOS / 128; t++) {
        __syncthreads();
        // K tile: thread -> one key row (32 floats = 8 float4), stride 36 floats
        {
            const float4* src = (const float4*)(kb + ((size_t)t * 128 + tid) * HD);
            float* dst = ksS + tid * KS_F;
#pragma unroll
            for (int i = 0; i < 8; i++)
                *(float4*)(dst + i * 4) = src[i];
        }
        // VT tile: 32 d-rows x 128 keys, stride 132 floats
        {
#pragma unroll
            for (int i = 0; i < 8; i++) {
                int idx = tid + i * 128;        // 0..1023 float4
                int row = idx >> 5, c = idx & 31;
                *(float4*)(vtS + row * VT_F + c * 4) =
                    *(const float4*)(vtb + (size_t)row * NPOS + t * 128 + c * 4);
            }
        }
        {
            int kk = t * 128 + tid;
            int kr = kk / GW;
            krf[tid] = (float)kr;
            kcf[tid] = (float)(kk - kr * GW);
        }
        __syncthreads();

#pragma unroll
        for (int gr = 0; gr < 16; gr++) {     // 16 groups of 8 keys
            // ---- QK^T: S[16 rows x 8 keys] over 4 k-steps ----
            float sf[4] = {0.f, 0.f, 0.f, 0.f};
            const float* krow = ksS + (gr * 8 + grp) * KS_F;
#pragma unroll
            for (int s = 0; s < 4; s++) {
                uint32_t b0 = __float_as_uint(krow[s * 8 + t4]);
                uint32_t b1 = __float_as_uint(krow[s * 8 + t4 + 4]);
                mma_tf32(sf, qA[s], b0, b1, sf);
            }
            // ---- softmax numerator; p rounded to tf32 for PV/l consistency ----
            int col = gr * 8 + t4 * 2;
            float kra = krf[col], kca = kcf[col];
            float krb = krf[col + 1], kcb = kcf[col + 1];
            uint32_t r0 = to_tf32(__expf(fmaf(decay, fabsf(qr0 - kra) + fabsf(qc0 - kca), sf[0])));
            uint32_t r1 = to_tf32(__expf(fmaf(decay, fabsf(qr0 - krb) + fabsf(qc0 - kcb), sf[1])));
            uint32_t r2 = to_tf32(__expf(fmaf(decay, fabsf(qr1 - kra) + fabsf(qc1 - kca), sf[2])));
            uint32_t r3 = to_tf32(__expf(fmaf(decay, fabsf(qr1 - krb) + fabsf(qc1 - kcb), sf[3])));
            l0 += __uint_as_float(r0) + __uint_as_float(r1);
            l1 += __uint_as_float(r2) + __uint_as_float(r3);

            // ---- repack C-frag (keys 2t4,2t4+1) to A-frag (keys t4, t4+4) ----
            const int srcA = (lane & ~3) | (t4 >> 1);
            const int srcB = srcA + 2;
            uint32_t x0 = __shfl_sync(0xFFFFFFFFu, r0, srcA);
            uint32_t x1 = __shfl_sync(0xFFFFFFFFu, r1, srcA);
            uint32_t y0 = __shfl_sync(0xFFFFFFFFu, r2, srcA);
            uint32_t y1 = __shfl_sync(0xFFFFFFFFu, r3, srcA);
            uint32_t z0 = __shfl_sync(0xFFFFFFFFu, r0, srcB);
            uint32_t z1 = __shfl_sync(0xFFFFFFFFu, r1, srcB);
            uint32_t w0 = __shfl_sync(0xFFFFFFFFu, r2, srcB);
            uint32_t w1 = __shfl_sync(0xFFFFFFFFu, r3, srcB);
            uint32_t aP[4];
            aP[0] = (t4 & 1) ? x1 : x0;   // row0, key t4
            aP[1] = (t4 & 1) ? y1 : y0;   // row1, key t4
            aP[2] = (t4 & 1) ? z1 : z0;   // row0, key t4+4
            aP[3] = (t4 & 1) ? w1 : w0;   // row1, key t4+4

            // ---- PV: O[16 x 32] += P[16 x 8keys] @ V[8keys x 32d] ----
#pragma unroll
            for (int nc = 0; nc < 4; nc++) {
                const float* vrow = vtS + (nc * 8 + grp) * VT_F + gr * 8;
                uint32_t b0 = __float_as_uint(vrow[t4]);
                uint32_t b1 = __float_as_uint(vrow[t4 + 4]);
                mma_tf32(o[nc], aP, b0, b1, o[nc]);
            }
        }
    }

    // reduce l over the 4 lanes sharing each row
    l0 += __shfl_xor_sync(0xFFFFFFFFu, l0, 1);
    l0 += __shfl_xor_sync(0xFFFFFFFFu, l0, 2);
    l1 += __shfl_xor_sync(0xFFFFFFFFu, l1, 1);
    l1 += __shfl_xor_sync(0xFFFFFFFFu, l1, 2);
    const float inv0 = 1.0f / l0;
    const float inv1 = 1.0f / l1;

#pragma unroll
    for (int nc = 0; nc < 4; nc++) {
        int d = h * HD + nc * 8 + t4 * 2;
        float2 w0 = make_float2(o[nc][0] * inv0, o[nc][1] * inv0);
        float2 w1 = make_float2(o[nc][2] * inv1, o[nc][3] * inv1);
        *(float2*)(g_attn + (size_t)(b * NPOS + qrow0) * CDIM + d) = w0;
        *(float2*)(g_attn + (size_t)(b * NPOS + qrow1) * CDIM + d) = w1;
    }
}

// ---------------------------------------------------------------------------
// Output GEMM: out = (g_attn + g_lepe) @ Wo + bo
// ---------------------------------------------------------------------------
__global__ __launch_bounds__(256) void out_gemm(
    const float* __restrict__ Wo, const float* __restrict__ bo,
    float* __restrict__ out)
{
    __shared__ float As[16][64];
    __shared__ float Bs[16][64];

    const int tid = threadIdx.x;
    const int tx = tid & 15, ty = tid >> 4;
    const int mb = blockIdx.x * 64, nb = blockIdx.y * 64;

    float acc[4][4];
#pragma unroll
    for (int i = 0; i < 4; i++)
#pragma unroll
        for (int j = 0; j < 4; j++) acc[i][j] = 0.f;

    const int ar = tid >> 2, ac4 = (tid & 3) * 4;
    const int br = tid >> 4, bc4 = (tid & 15) * 4;

    for (int k0 = 0; k0 < CDIM; k0 += 16) {
        size_t aoff = (size_t)(mb + ar) * CDIM + k0 + ac4;
        float4 a1 = *(const float4*)&g_attn[aoff];
        float4 a2 = *(const float4*)&g_lepe[aoff];
        As[ac4 + 0][ar] = a1.x + a2.x; As[ac4 + 1][ar] = a1.y + a2.y;
        As[ac4 + 2][ar] = a1.z + a2.z; As[ac4 + 3][ar] = a1.w + a2.w;
        *(float4*)&Bs[br][bc4] = *(const float4*)&Wo[(size_t)(k0 + br) * CDIM + nb + bc4];
        __syncthreads();
#pragma unroll
        for (int kk = 0; kk < 16; kk++) {
            float4 av = *(float4*)&As[kk][ty * 4];
            float4 bv4 = *(float4*)&Bs[kk][tx * 4];
            acc[0][0] += av.x * bv4.x; acc[0][1] += av.x * bv4.y;
            acc[0][2] += av.x * bv4.z; acc[0][3] += av.x * bv4.w;
            acc[1][0] += av.y * bv4.x; acc[1][1] += av.y * bv4.y;
            acc[1][2] += av.y * bv4.z; acc[1][3] += av.y * bv4.w;
            acc[2][0] += av.z * bv4.x; acc[2][1] += av.z * bv4.y;
            acc[2][2] += av.z * bv4.z; acc[2][3] += av.z * bv4.w;
            acc[3][0] += av.w * bv4.x; acc[3][1] += av.w * bv4.y;
            acc[3][2] += av.w * bv4.z; acc[3][3] += av.w * bv4.w;
        }
        __syncthreads();
    }

#pragma unroll
    for (int i = 0; i < 4; i++) {
        int row = mb + ty * 4 + i;
#pragma unroll
        for (int j = 0; j < 4; j++) {
            int col = nb + tx * 4 + j;
            out[(size_t)row * CDIM + col] = acc[i][j] + bo[col];
        }
    }
}

// ---------------------------------------------------------------------------
extern "C" void kernel_launch(void* const* d_in, const int* in_sizes, int n_in,
                              void* d_out, int out_size)
{
    const float* x      = (const float*)d_in[0];
    const float* Wq     = (const float*)d_in[1];
    const float* bq     = (const float*)d_in[2];
    const float* Wk     = (const float*)d_in[3];
    const float* bk     = (const float*)d_in[4];
    const float* Wv     = (const float*)d_in[5];
    const float* bv     = (const float*)d_in[6];
    const float* lepe_w = (const float*)d_in[7];
    const float* lepe_b = (const float*)d_in[8];
    const float* Wo     = (const float*)d_in[9];
    const float* bo     = (const float*)d_in[10];
    float* out = (float*)d_out;

    rotary_table<<<(NPOS * 16 + 255) / 256, 256>>>();
    transpose_w<<<(25 * CDIM + 255) / 256, 256>>>(lepe_w);

    dim3 g1(MTOT / 64, CDIM / 64, 3);
    qkv_gemm<<<g1, 256>>>(x, Wq, bq, Wk, bk, Wv, bv);

    dim3 gv(NPOS / 32, BH);
    vt_kernel<<<gv, dim3(32, 8)>>>();

    dwconv<<<MTOT, 256>>>(lepe_b);

    dim3 g3(NPOS / 64, BH);
    attn_mma<<<g3, 128>>>();

    dim3 g4(MTOT / 64, CDIM / 64);
    out_gemm<<<g4, 256>>>(Wo, bo, out);
}

// round 11
// speedup vs baseline: 4.5893x; 1.4098x over previous
#include <cuda_runtime.h>
#include <math.h>
#include <cstdint>

#define HEADS 8
#define HD 32
#define NPOS 2304
#define GW 48
#define CDIM 256
#define BATCH 2
#define MTOT (BATCH*NPOS)   // 4608
#define BH (BATCH*HEADS)    // 16

// Scratch (static device arrays; no allocation allowed)
__device__ float g_v[BATCH*HEADS*NPOS*HD];    // [bh][n][d] fp32 (dwconv, vt source)
__device__ float g_q[BATCH*HEADS*NPOS*HD];    // [bh][n][d] rotary q, tf32-rounded
__device__ float g_k[BATCH*HEADS*NPOS*HD];    // [bh][n][d] rotary scaled k, tf32-rounded
__device__ float g_vt[BATCH*HEADS*HD*NPOS];   // [bh][d][n] V transposed, tf32-rounded
__device__ float g_lepe[BATCH*NPOS*CDIM];
__device__ float g_attn[BATCH*NPOS*CDIM];
__device__ float g_wt[25*CDIM];
__device__ float g_sin[NPOS*16];
__device__ float g_cos[NPOS*16];

// ---- tf32 helpers ----------------------------------------------------------
__device__ __forceinline__ uint32_t to_tf32(float f)
{
    uint32_t r;
    asm("cvt.rna.tf32.f32 %0, %1;" : "=r"(r) : "f"(f));
    return r;
}
__device__ __forceinline__ float to_tf32f(float f)
{
    return __uint_as_float(to_tf32(f));
}
__device__ __forceinline__ void mma_tf32(
    float* d, const uint32_t* a, uint32_t b0, uint32_t b1, const float* c)
{
    asm volatile(
        "mma.sync.aligned.m16n8k8.row.col.f32.tf32.tf32.f32 "
        "{%0,%1,%2,%3}, {%4,%5,%6,%7}, {%8,%9}, {%10,%11,%12,%13};"
        : "=f"(d[0]), "=f"(d[1]), "=f"(d[2]), "=f"(d[3])
        : "r"(a[0]), "r"(a[1]), "r"(a[2]), "r"(a[3]),
          "r"(b0), "r"(b1),
          "f"(c[0]), "f"(c[1]), "f"(c[2]), "f"(c[3]));
}

// ---------------------------------------------------------------------------
__global__ void rotary_table()
{
    int t = blockIdx.x * 256 + threadIdx.x;
    if (t < NPOS * 16) {
        int pos = t >> 4, pj = t & 15;
        float ang = expf(-(float)pj * (9.210340371976184f / 15.0f));
        float s, c;
        sincosf((float)pos * ang, &s, &c);
        g_sin[t] = s;
        g_cos[t] = c;
    }
}

// ---------------------------------------------------------------------------
// tf32-mma QKV GEMM: y = x @ W + b; 128 threads, BM=128, BN=64, BK=32.
// Inputs rna-rounded to tf32 during smem fill. Epilogue: rotary (q/k) or v.
// grid (MTOT/128, CDIM/64, 3)
// ---------------------------------------------------------------------------
#define XS 36   // x tile row stride (floats)
#define WS 72   // W tile row stride (floats); 72 % 32 == 8 -> conflict-free B frags

__global__ __launch_bounds__(128) void qkv_mma(
    const float* __restrict__ x,
    const float* __restrict__ Wq, const float* __restrict__ bq,
    const float* __restrict__ Wk, const float* __restrict__ bk,
    const float* __restrict__ Wv, const float* __restrict__ bv)
{
    const int which = blockIdx.z;
    const float* __restrict__ W    = (which == 0) ? Wq : (which == 1 ? Wk : Wv);
    const float* __restrict__ bias = (which == 0) ? bq : (which == 1 ? bk : bv);

    __shared__ __align__(16) float xs[128 * XS];   // 18432 B
    __shared__ __align__(16) float ws[32 * WS];    //  9216 B

    const int tid = threadIdx.x;
    const int lane = tid & 31, wid = tid >> 5;
    const int grp = lane >> 2, t4 = lane & 3;
    const int mb = blockIdx.x * 128, nb = blockIdx.y * 64;

    float acc[2][8][4];
#pragma unroll
    for (int mi = 0; mi < 2; mi++)
#pragma unroll
        for (int n = 0; n < 8; n++)
#pragma unroll
            for (int j = 0; j < 4; j++) acc[mi][n][j] = 0.f;

    for (int k0 = 0; k0 < CDIM; k0 += 32) {
        __syncthreads();
        // x tile: 128 rows x 32 floats (8 float4/row), tf32-rounded
#pragma unroll
        for (int i = 0; i < 8; i++) {
            int idx = tid + i * 128;
            int row = idx >> 3, c = idx & 7;
            float4 a = *(const float4*)&x[(size_t)(mb + row) * CDIM + k0 + c * 4];
            a.x = to_tf32f(a.x); a.y = to_tf32f(a.y);
            a.z = to_tf32f(a.z); a.w = to_tf32f(a.w);
            *(float4*)(xs + row * XS + c * 4) = a;
        }
        // W tile: 32 rows x 64 floats (16 float4/row), tf32-rounded
#pragma unroll
        for (int i = 0; i < 4; i++) {
            int idx = tid + i * 128;
            int row = idx >> 4, c = idx & 15;
            float4 a = *(const float4*)&W[(size_t)(k0 + row) * CDIM + nb + c * 4];
            a.x = to_tf32f(a.x); a.y = to_tf32f(a.y);
            a.z = to_tf32f(a.z); a.w = to_tf32f(a.w);
            *(float4*)(ws + row * WS + c * 4) = a;
        }
        __syncthreads();

#pragma unroll
        for (int ks = 0; ks < 4; ks++) {
            uint32_t bf[8][2];
#pragma unroll
            for (int n = 0; n < 8; n++) {
                bf[n][0] = __float_as_uint(ws[(ks * 8 + t4) * WS + n * 8 + grp]);
                bf[n][1] = __float_as_uint(ws[(ks * 8 + t4 + 4) * WS + n * 8 + grp]);
            }
            uint32_t af[2][4];
#pragma unroll
            for (int mi = 0; mi < 2; mi++) {
                const float* xrow = xs + (wid * 32 + mi * 16 + grp) * XS + ks * 8;
                const float* xrow8 = xrow + 8 * XS;
                af[mi][0] = __float_as_uint(xrow[t4]);
                af[mi][1] = __float_as_uint(xrow8[t4]);
                af[mi][2] = __float_as_uint(xrow[t4 + 4]);
                af[mi][3] = __float_as_uint(xrow8[t4 + 4]);
            }
#pragma unroll
            for (int mi = 0; mi < 2; mi++)
#pragma unroll
                for (int n = 0; n < 8; n++)
                    mma_tf32(acc[mi][n], af[mi], bf[n][0], bf[n][1], acc[mi][n]);
        }
    }

    const float scal = (which == 1) ? 0.17677669529663687f : 1.0f;

#pragma unroll
    for (int mi = 0; mi < 2; mi++) {
#pragma unroll
        for (int rh = 0; rh < 2; rh++) {
            int row = mb + wid * 32 + mi * 16 + rh * 8 + grp;
            int b = (row >= NPOS) ? 1 : 0;
            int pos = row - b * NPOS;
#pragma unroll
            for (int n = 0; n < 8; n++) {
                int col = nb + n * 8 + 2 * t4;
                float v0 = acc[mi][n][rh * 2 + 0] + bias[col];
                float v1 = acc[mi][n][rh * 2 + 1] + bias[col + 1];
                size_t base = (((size_t)(b * HEADS + (col >> 5))) * NPOS + pos) * HD + (col & 31);
                if (which == 2) {
                    *(float2*)&g_v[base] = make_float2(v0, v1);
                } else {
                    int pj = (col & 31) >> 1;
                    float s = g_sin[pos * 16 + pj];
                    float c = g_cos[pos * 16 + pj];
                    v0 *= scal; v1 *= scal;
                    float* dst = (which == 0) ? g_q : g_k;
                    *(float2*)&dst[base] =
                        make_float2(to_tf32f(v0 * c - v1 * s), to_tf32f(v1 * c + v0 * s));
                }
            }
        }
    }
}

// ---------------------------------------------------------------------------
// Transpose V: [bh][n][d] fp32 -> [bh][d][n] tf32-rounded fp32
// ---------------------------------------------------------------------------
__global__ __launch_bounds__(256) void vt_kernel()
{
    __shared__ float tile[32][33];
    const int bh = blockIdx.y;
    const int p0 = blockIdx.x * 32;
    const int tx = threadIdx.x, ty = threadIdx.y;
#pragma unroll
    for (int i = 0; i < 4; i++) {
        int row = ty + i * 8;
        tile[row][tx] = g_v[((size_t)bh * NPOS + p0 + row) * HD + tx];
    }
    __syncthreads();
#pragma unroll
    for (int i = 0; i < 4; i++) {
        int d = ty + i * 8;
        g_vt[((size_t)bh * HD + d) * NPOS + p0 + tx] = to_tf32f(tile[tx][d]);
    }
}

// ---------------------------------------------------------------------------
__global__ void transpose_w(const float* __restrict__ lw)
{
    int t = blockIdx.x * 256 + threadIdx.x;
    if (t < 25 * CDIM) {
        int ch = t / 25, tap = t - ch * 25;
        g_wt[tap * CDIM + ch] = lw[t];
    }
}

// ---------------------------------------------------------------------------
__global__ __launch_bounds__(256) void dwconv(const float* __restrict__ lepe_b)
{
    int t = blockIdx.x * 256 + threadIdx.x;
    int ch = t & 255;
    int sp = t >> 8;
    int b = sp / NPOS;
    int pos = sp - b * NPOS;
    int r = pos / GW, c = pos - (pos / GW) * GW;
    const float* vb = g_v + ((size_t)(b * HEADS + (ch >> 5)) * NPOS) * HD + (ch & 31);
    float sum = lepe_b[ch];
#pragma unroll
    for (int i = 0; i < 5; i++) {
        int rr = r + i - 2;
        if ((unsigned)rr < GW) {
#pragma unroll
            for (int j = 0; j < 5; j++) {
                int cc = c + j - 2;
                if ((unsigned)cc < GW) {
                    sum += vb[(size_t)(rr * GW + cc) * HD] * g_wt[(i * 5 + j) * CDIM + ch];
                }
            }
        }
    }
    g_lepe[t] = sum;
}

// ---------------------------------------------------------------------------
// Flash attention via tf32 mma, shuffle-free via key permutation.
// QK B-operand reads key row sigma(grp) = (grp>>1)+((grp&1)<<2) within each
// 8-key group; then the C-fragment (logical cols 2t4, 2t4+1) holds physical
// keys {t4, t4+4} == exactly the PV A-fragment layout. V stays in natural
// order. grid (NPOS/64, BH), block 128.
// ---------------------------------------------------------------------------
#define KS_F 36
#define VT_F 132

__global__ __launch_bounds__(128) void attn_mma()
{
    __shared__ __align__(16) float ksS[128 * KS_F];   // 18432 B
    __shared__ __align__(16) float vtS[32 * VT_F];    // 16896 B
    __shared__ float krf[128], kcf[128];

    const int tid = threadIdx.x;
    const int lane = tid & 31, wid = tid >> 5;
    const int grp = lane >> 2, t4 = lane & 3;
    const int sg = (grp >> 1) + ((grp & 1) << 2);   // sigma(grp)
    const int bh = blockIdx.y, h = bh & 7, b = bh >> 3;
    const int q0 = blockIdx.x * 64;
    const int qrow0 = q0 + wid * 16 + grp;
    const int qrow1 = qrow0 + 8;

    uint32_t qA[4][4];
    {
        const float* qb = g_q + (size_t)bh * NPOS * HD;
#pragma unroll
        for (int s = 0; s < 4; s++) {
            qA[s][0] = __float_as_uint(qb[(size_t)qrow0 * HD + s * 8 + t4]);
            qA[s][1] = __float_as_uint(qb[(size_t)qrow1 * HD + s * 8 + t4]);
            qA[s][2] = __float_as_uint(qb[(size_t)qrow0 * HD + s * 8 + t4 + 4]);
            qA[s][3] = __float_as_uint(qb[(size_t)qrow1 * HD + s * 8 + t4 + 4]);
        }
    }

    float o[4][4];
#pragma unroll
    for (int i = 0; i < 4; i++)
#pragma unroll
        for (int j = 0; j < 4; j++) o[i][j] = 0.f;
    float l0 = 0.f, l1 = 0.f;

    const int qr0i = qrow0 / GW;
    const float qr0 = (float)qr0i, qc0 = (float)(qrow0 - qr0i * GW);
    const int qr1i = qrow1 / GW;
    const float qr1 = (float)qr1i, qc1 = (float)(qrow1 - qr1i * GW);
    const float decay = logf(1.0f - exp2f(-(1.0f + 0.375f * (float)h)));

    const float* kb = g_k + (size_t)bh * NPOS * HD;
    const float* vtb = g_vt + (size_t)bh * HD * NPOS;

    for (int t = 0; t < NPOS / 128; t++) {
        __syncthreads();
        {
            const float4* src = (const float4*)(kb + ((size_t)t * 128 + tid) * HD);
            float* dst = ksS + tid * KS_F;
#pragma unroll
            for (int i = 0; i < 8; i++)
                *(float4*)(dst + i * 4) = src[i];
        }
        {
#pragma unroll
            for (int i = 0; i < 8; i++) {
                int idx = tid + i * 128;
                int row = idx >> 5, c = idx & 31;
                *(float4*)(vtS + row * VT_F + c * 4) =
                    *(const float4*)(vtb + (size_t)row * NPOS + t * 128 + c * 4);
            }
        }
        {
            int kk = t * 128 + tid;
            int kr = kk / GW;
            krf[tid] = (float)kr;
            kcf[tid] = (float)(kk - kr * GW);
        }
        __syncthreads();

#pragma unroll
        for (int gr = 0; gr < 16; gr++) {
            // ---- QK^T with permuted key columns ----
            float sf[4] = {0.f, 0.f, 0.f, 0.f};
            const float* krow = ksS + (gr * 8 + sg) * KS_F;
#pragma unroll
            for (int s = 0; s < 4; s++) {
                uint32_t b0 = __float_as_uint(krow[s * 8 + t4]);
                uint32_t b1 = __float_as_uint(krow[s * 8 + t4 + 4]);
                mma_tf32(sf, qA[s], b0, b1, sf);
            }
            // C-frag now holds physical keys col0 = gr*8+t4, col1 = col0+4
            int col0 = gr * 8 + t4;
            int col1 = col0 + 4;
            float kra = krf[col0], kca = kcf[col0];
            float krb = krf[col1], kcb = kcf[col1];
            float p0 = to_tf32f(__expf(fmaf(decay, fabsf(qr0 - kra) + fabsf(qc0 - kca), sf[0])));
            float p1 = to_tf32f(__expf(fmaf(decay, fabsf(qr0 - krb) + fabsf(qc0 - kcb), sf[1])));
            float p2 = to_tf32f(__expf(fmaf(decay, fabsf(qr1 - kra) + fabsf(qc1 - kca), sf[2])));
            float p3 = to_tf32f(__expf(fmaf(decay, fabsf(qr1 - krb) + fabsf(qc1 - kcb), sf[3])));
            l0 += p0 + p1;
            l1 += p2 + p3;
            uint32_t aP[4];
            aP[0] = __float_as_uint(p0);   // (row0, key t4)
            aP[1] = __float_as_uint(p2);   // (row1, key t4)
            aP[2] = __float_as_uint(p1);   // (row0, key t4+4)
            aP[3] = __float_as_uint(p3);   // (row1, key t4+4)

            // ---- PV: O[16 x 32] += P[16 x 8keys] @ V[8keys x 32d] ----
#pragma unroll
            for (int nc = 0; nc < 4; nc++) {
                const float* vrow = vtS + (nc * 8 + grp) * VT_F + gr * 8;
                uint32_t b0 = __float_as_uint(vrow[t4]);
                uint32_t b1 = __float_as_uint(vrow[t4 + 4]);
                mma_tf32(o[nc], aP, b0, b1, o[nc]);
            }
        }
    }

    l0 += __shfl_xor_sync(0xFFFFFFFFu, l0, 1);
    l0 += __shfl_xor_sync(0xFFFFFFFFu, l0, 2);
    l1 += __shfl_xor_sync(0xFFFFFFFFu, l1, 1);
    l1 += __shfl_xor_sync(0xFFFFFFFFu, l1, 2);
    const float inv0 = 1.0f / l0;
    const float inv1 = 1.0f / l1;

#pragma unroll
    for (int nc = 0; nc < 4; nc++) {
        int d = h * HD + nc * 8 + t4 * 2;
        float2 w0 = make_float2(o[nc][0] * inv0, o[nc][1] * inv0);
        float2 w1 = make_float2(o[nc][2] * inv1, o[nc][3] * inv1);
        *(float2*)(g_attn + (size_t)(b * NPOS + qrow0) * CDIM + d) = w0;
        *(float2*)(g_attn + (size_t)(b * NPOS + qrow1) * CDIM + d) = w1;
    }
}

// ---------------------------------------------------------------------------
// tf32-mma output GEMM: out = (g_attn + g_lepe) @ Wo + bo
// Same scheme as qkv_mma; A = attn+lepe fused on smem fill.
// grid (MTOT/128, CDIM/64)
// ---------------------------------------------------------------------------
__global__ __launch_bounds__(128) void out_mma(
    const float* __restrict__ Wo, const float* __restrict__ bo,
    float* __restrict__ out)
{
    __shared__ __align__(16) float xs[128 * XS];
    __shared__ __align__(16) float ws[32 * WS];

    const int tid = threadIdx.x;
    const int lane = tid & 31, wid = tid >> 5;
    const int grp = lane >> 2, t4 = lane & 3;
    const int mb = blockIdx.x * 128, nb = blockIdx.y * 64;

    float acc[2][8][4];
#pragma unroll
    for (int mi = 0; mi < 2; mi++)
#pragma unroll
        for (int n = 0; n < 8; n++)
#pragma unroll
            for (int j = 0; j < 4; j++) acc[mi][n][j] = 0.f;

    for (int k0 = 0; k0 < CDIM; k0 += 32) {
        __syncthreads();
#pragma unroll
        for (int i = 0; i < 8; i++) {
            int idx = tid + i * 128;
            int row = idx >> 3, c = idx & 7;
            size_t off = (size_t)(mb + row) * CDIM + k0 + c * 4;
            float4 a = *(const float4*)&g_attn[off];
            float4 e = *(const float4*)&g_lepe[off];
            a.x = to_tf32f(a.x + e.x); a.y = to_tf32f(a.y + e.y);
            a.z = to_tf32f(a.z + e.z); a.w = to_tf32f(a.w + e.w);
            *(float4*)(xs + row * XS + c * 4) = a;
        }
#pragma unroll
        for (int i = 0; i < 4; i++) {
            int idx = tid + i * 128;
            int row = idx >> 4, c = idx & 15;
            float4 a = *(const float4*)&Wo[(size_t)(k0 + row) * CDIM + nb + c * 4];
            a.x = to_tf32f(a.x); a.y = to_tf32f(a.y);
            a.z = to_tf32f(a.z); a.w = to_tf32f(a.w);
            *(float4*)(ws + row * WS + c * 4) = a;
        }
        __syncthreads();

#pragma unroll
        for (int ks = 0; ks < 4; ks++) {
            uint32_t bf[8][2];
#pragma unroll
            for (int n = 0; n < 8; n++) {
                bf[n][0] = __float_as_uint(ws[(ks * 8 + t4) * WS + n * 8 + grp]);
                bf[n][1] = __float_as_uint(ws[(ks * 8 + t4 + 4) * WS + n * 8 + grp]);
            }
            uint32_t af[2][4];
#pragma unroll
            for (int mi = 0; mi < 2; mi++) {
                const float* xrow = xs + (wid * 32 + mi * 16 + grp) * XS + ks * 8;
                const float* xrow8 = xrow + 8 * XS;
                af[mi][0] = __float_as_uint(xrow[t4]);
                af[mi][1] = __float_as_uint(xrow8[t4]);
                af[mi][2] = __float_as_uint(xrow[t4 + 4]);
                af[mi][3] = __float_as_uint(xrow8[t4 + 4]);
            }
#pragma unroll
            for (int mi = 0; mi < 2; mi++)
#pragma unroll
                for (int n = 0; n < 8; n++)
                    mma_tf32(acc[mi][n], af[mi], bf[n][0], bf[n][1], acc[mi][n]);
        }
    }

#pragma unroll
    for (int mi = 0; mi < 2; mi++) {
#pragma unroll
        for (int rh = 0; rh < 2; rh++) {
            int row = mb + wid * 32 + mi * 16 + rh * 8 + grp;
#pragma unroll
            for (int n = 0; n < 8; n++) {
                int col = nb + n * 8 + 2 * t4;
                float v0 = acc[mi][n][rh * 2 + 0] + bo[col];
                float v1 = acc[mi][n][rh * 2 + 1] + bo[col + 1];
                *(float2*)&out[(size_t)row * CDIM + col] = make_float2(v0, v1);
            }
        }
    }
}

// ---------------------------------------------------------------------------
extern "C" void kernel_launch(void* const* d_in, const int* in_sizes, int n_in,
                              void* d_out, int out_size)
{
    const float* x      = (const float*)d_in[0];
    const float* Wq     = (const float*)d_in[1];
    const float* bq     = (const float*)d_in[2];
    const float* Wk     = (const float*)d_in[3];
    const float* bk     = (const float*)d_in[4];
    const float* Wv     = (const float*)d_in[5];
    const float* bv     = (const float*)d_in[6];
    const float* lepe_w = (const float*)d_in[7];
    const float* lepe_b = (const float*)d_in[8];
    const float* Wo     = (const float*)d_in[9];
    const float* bo     = (const float*)d_in[10];
    float* out = (float*)d_out;

    rotary_table<<<(NPOS * 16 + 255) / 256, 256>>>();
    transpose_w<<<(25 * CDIM + 255) / 256, 256>>>(lepe_w);

    dim3 g1(MTOT / 128, CDIM / 64, 3);
    qkv_mma<<<g1, 128>>>(x, Wq, bq, Wk, bk, Wv, bv);

    dim3 gv(NPOS / 32, BH);
    vt_kernel<<<gv, dim3(32, 8)>>>();

    dwconv<<<MTOT, 256>>>(lepe_b);

    dim3 g3(NPOS / 64, BH);
    attn_mma<<<g3, 128>>>();

    dim3 g4(MTOT / 128, CDIM / 64);
    out_mma<<<g4, 128>>>(Wo, bo, out);
}

// round 12
// speedup vs baseline: 5.7548x; 1.2539x over previous
#include <cuda_runtime.h>
#include <math.h>
#include <cstdint>

#define HEADS 8
#define HD 32
#define NPOS 2304
#define GW 48
#define CDIM 256
#define BATCH 2
#define MTOT (BATCH*NPOS)   // 4608
#define BH (BATCH*HEADS)    // 16

// Scratch (static device arrays; no allocation allowed)
__device__ float g_v[BATCH*HEADS*NPOS*HD];    // [bh][n][d] fp32 (dwconv, vt source)
__device__ float g_q[BATCH*HEADS*NPOS*HD];    // [bh][n][d] rotary q, tf32-rounded
__device__ float g_k[BATCH*HEADS*NPOS*HD];    // [bh][n][d] rotary scaled k, tf32-rounded
__device__ float g_vt[BATCH*HEADS*HD*NPOS];   // [bh][d][n] V transposed, tf32-rounded
__device__ float g_lepe[BATCH*NPOS*CDIM];
__device__ float g_attn[BATCH*NPOS*CDIM];
__device__ float g_wt[25*CDIM];
__device__ float g_sin[NPOS*16];
__device__ float g_cos[NPOS*16];

// ---- tf32 helpers ----------------------------------------------------------
__device__ __forceinline__ uint32_t to_tf32(float f)
{
    uint32_t r;
    asm("cvt.rna.tf32.f32 %0, %1;" : "=r"(r) : "f"(f));
    return r;
}
__device__ __forceinline__ float to_tf32f(float f)
{
    return __uint_as_float(to_tf32(f));
}
__device__ __forceinline__ void mma_tf32(
    float* d, const uint32_t* a, uint32_t b0, uint32_t b1, const float* c)
{
    asm volatile(
        "mma.sync.aligned.m16n8k8.row.col.f32.tf32.tf32.f32 "
        "{%0,%1,%2,%3}, {%4,%5,%6,%7}, {%8,%9}, {%10,%11,%12,%13};"
        : "=f"(d[0]), "=f"(d[1]), "=f"(d[2]), "=f"(d[3])
        : "r"(a[0]), "r"(a[1]), "r"(a[2]), "r"(a[3]),
          "r"(b0), "r"(b1),
          "f"(c[0]), "f"(c[1]), "f"(c[2]), "f"(c[3]));
}
__device__ __forceinline__ uint32_t smem_u32(const void* p)
{
    uint32_t a;
    asm("{ .reg .u64 t; cvta.to.shared.u64 t, %1; cvt.u32.u64 %0, t; }" : "=r"(a) : "l"(p));
    return a;
}
__device__ __forceinline__ void cpa16(uint32_t saddr, const void* g)
{
    asm volatile("cp.async.cg.shared.global [%0], [%1], 16;" :: "r"(saddr), "l"(g));
}

// ---------------------------------------------------------------------------
__global__ void rotary_table()
{
    int t = blockIdx.x * 256 + threadIdx.x;
    if (t < NPOS * 16) {
        int pos = t >> 4, pj = t & 15;
        float ang = expf(-(float)pj * (9.210340371976184f / 15.0f));
        float s, c;
        sincosf((float)pos * ang, &s, &c);
        g_sin[t] = s;
        g_cos[t] = c;
    }
}

// ---------------------------------------------------------------------------
// tf32-mma QKV GEMM: y = x @ W + b; 128 threads, BM=128, BN=64, BK=32.
// grid (MTOT/128, CDIM/64, 3)
// ---------------------------------------------------------------------------
#define XS 36   // x tile row stride (floats)
#define WS 72   // W tile row stride (floats)

__global__ __launch_bounds__(128) void qkv_mma(
    const float* __restrict__ x,
    const float* __restrict__ Wq, const float* __restrict__ bq,
    const float* __restrict__ Wk, const float* __restrict__ bk,
    const float* __restrict__ Wv, const float* __restrict__ bv)
{
    const int which = blockIdx.z;
    const float* __restrict__ W    = (which == 0) ? Wq : (which == 1 ? Wk : Wv);
    const float* __restrict__ bias = (which == 0) ? bq : (which == 1 ? bk : bv);

    __shared__ __align__(16) float xs[128 * XS];
    __shared__ __align__(16) float ws[32 * WS];

    const int tid = threadIdx.x;
    const int lane = tid & 31, wid = tid >> 5;
    const int grp = lane >> 2, t4 = lane & 3;
    const int mb = blockIdx.x * 128, nb = blockIdx.y * 64;

    float acc[2][8][4];
#pragma unroll
    for (int mi = 0; mi < 2; mi++)
#pragma unroll
        for (int n = 0; n < 8; n++)
#pragma unroll
            for (int j = 0; j < 4; j++) acc[mi][n][j] = 0.f;

    for (int k0 = 0; k0 < CDIM; k0 += 32) {
        __syncthreads();
#pragma unroll
        for (int i = 0; i < 8; i++) {
            int idx = tid + i * 128;
            int row = idx >> 3, c = idx & 7;
            float4 a = *(const float4*)&x[(size_t)(mb + row) * CDIM + k0 + c * 4];
            a.x = to_tf32f(a.x); a.y = to_tf32f(a.y);
            a.z = to_tf32f(a.z); a.w = to_tf32f(a.w);
            *(float4*)(xs + row * XS + c * 4) = a;
        }
#pragma unroll
        for (int i = 0; i < 4; i++) {
            int idx = tid + i * 128;
            int row = idx >> 4, c = idx & 15;
            float4 a = *(const float4*)&W[(size_t)(k0 + row) * CDIM + nb + c * 4];
            a.x = to_tf32f(a.x); a.y = to_tf32f(a.y);
            a.z = to_tf32f(a.z); a.w = to_tf32f(a.w);
            *(float4*)(ws + row * WS + c * 4) = a;
        }
        __syncthreads();

#pragma unroll
        for (int ks = 0; ks < 4; ks++) {
            uint32_t bf[8][2];
#pragma unroll
            for (int n = 0; n < 8; n++) {
                bf[n][0] = __float_as_uint(ws[(ks * 8 + t4) * WS + n * 8 + grp]);
                bf[n][1] = __float_as_uint(ws[(ks * 8 + t4 + 4) * WS + n * 8 + grp]);
            }
            uint32_t af[2][4];
#pragma unroll
            for (int mi = 0; mi < 2; mi++) {
                const float* xrow = xs + (wid * 32 + mi * 16 + grp) * XS + ks * 8;
                const float* xrow8 = xrow + 8 * XS;
                af[mi][0] = __float_as_uint(xrow[t4]);
                af[mi][1] = __float_as_uint(xrow8[t4]);
                af[mi][2] = __float_as_uint(xrow[t4 + 4]);
                af[mi][3] = __float_as_uint(xrow8[t4 + 4]);
            }
#pragma unroll
            for (int mi = 0; mi < 2; mi++)
#pragma unroll
                for (int n = 0; n < 8; n++)
                    mma_tf32(acc[mi][n], af[mi], bf[n][0], bf[n][1], acc[mi][n]);
        }
    }

    const float scal = (which == 1) ? 0.17677669529663687f : 1.0f;

#pragma unroll
    for (int mi = 0; mi < 2; mi++) {
#pragma unroll
        for (int rh = 0; rh < 2; rh++) {
            int row = mb + wid * 32 + mi * 16 + rh * 8 + grp;
            int b = (row >= NPOS) ? 1 : 0;
            int pos = row - b * NPOS;
#pragma unroll
            for (int n = 0; n < 8; n++) {
                int col = nb + n * 8 + 2 * t4;
                float v0 = acc[mi][n][rh * 2 + 0] + bias[col];
                float v1 = acc[mi][n][rh * 2 + 1] + bias[col + 1];
                size_t base = (((size_t)(b * HEADS + (col >> 5))) * NPOS + pos) * HD + (col & 31);
                if (which == 2) {
                    *(float2*)&g_v[base] = make_float2(v0, v1);
                } else {
                    int pj = (col & 31) >> 1;
                    float s = g_sin[pos * 16 + pj];
                    float c = g_cos[pos * 16 + pj];
                    v0 *= scal; v1 *= scal;
                    float* dst = (which == 0) ? g_q : g_k;
                    *(float2*)&dst[base] =
                        make_float2(to_tf32f(v0 * c - v1 * s), to_tf32f(v1 * c + v0 * s));
                }
            }
        }
    }
}

// ---------------------------------------------------------------------------
// Transpose V: [bh][n][d] fp32 -> [bh][d][n] tf32-rounded fp32
// ---------------------------------------------------------------------------
__global__ __launch_bounds__(256) void vt_kernel()
{
    __shared__ float tile[32][33];
    const int bh = blockIdx.y;
    const int p0 = blockIdx.x * 32;
    const int tx = threadIdx.x, ty = threadIdx.y;
#pragma unroll
    for (int i = 0; i < 4; i++) {
        int row = ty + i * 8;
        tile[row][tx] = g_v[((size_t)bh * NPOS + p0 + row) * HD + tx];
    }
    __syncthreads();
#pragma unroll
    for (int i = 0; i < 4; i++) {
        int d = ty + i * 8;
        g_vt[((size_t)bh * HD + d) * NPOS + p0 + tx] = to_tf32f(tile[tx][d]);
    }
}

// ---------------------------------------------------------------------------
__global__ void transpose_w(const float* __restrict__ lw)
{
    int t = blockIdx.x * 256 + threadIdx.x;
    if (t < 25 * CDIM) {
        int ch = t / 25, tap = t - ch * 25;
        g_wt[tap * CDIM + ch] = lw[t];
    }
}

// ---------------------------------------------------------------------------
__global__ __launch_bounds__(256) void dwconv(const float* __restrict__ lepe_b)
{
    int t = blockIdx.x * 256 + threadIdx.x;
    int ch = t & 255;
    int sp = t >> 8;
    int b = sp / NPOS;
    int pos = sp - b * NPOS;
    int r = pos / GW, c = pos - (pos / GW) * GW;
    const float* vb = g_v + ((size_t)(b * HEADS + (ch >> 5)) * NPOS) * HD + (ch & 31);
    float sum = lepe_b[ch];
#pragma unroll
    for (int i = 0; i < 5; i++) {
        int rr = r + i - 2;
        if ((unsigned)rr < GW) {
#pragma unroll
            for (int j = 0; j < 5; j++) {
                int cc = c + j - 2;
                if ((unsigned)cc < GW) {
                    sum += vb[(size_t)(rr * GW + cc) * HD] * g_wt[(i * 5 + j) * CDIM + ch];
                }
            }
        }
    }
    g_lepe[t] = sum;
}

// ---------------------------------------------------------------------------
// Flash attention: tf32 mma, shuffle-free (key-permutation), 256 threads,
// 128 queries/block, double-buffered cp.async K/V tile pipeline.
// grid (NPOS/128 = 18, BH), dynamic smem = 2 buffers x 36352 B.
// Buffer layout (floats): ks[128*36] | vt[32*132] | krf[128] | kcf[128]
// ---------------------------------------------------------------------------
#define KS_F 36
#define VT_F 132
#define ABUF 9088              // floats per buffer
#define AOFF_VT 4608
#define AOFF_KR 8832
#define AOFF_KC 8960

__global__ __launch_bounds__(256) void attn_pipe()
{
    extern __shared__ __align__(16) float dyn[];
    const uint32_t sbase = smem_u32(dyn);

    const int tid = threadIdx.x;
    const int lane = tid & 31, wid = tid >> 5;
    const int grp = lane >> 2, t4 = lane & 3;
    const int sg = (grp >> 1) + ((grp & 1) << 2);   // sigma(grp)
    const int bh = blockIdx.y, h = bh & 7, b = bh >> 3;
    const int q0 = blockIdx.x * 128;
    const int qrow0 = q0 + wid * 16 + grp;
    const int qrow1 = qrow0 + 8;

    uint32_t qA[4][4];
    {
        const float* qb = g_q + (size_t)bh * NPOS * HD;
#pragma unroll
        for (int s = 0; s < 4; s++) {
            qA[s][0] = __float_as_uint(qb[(size_t)qrow0 * HD + s * 8 + t4]);
            qA[s][1] = __float_as_uint(qb[(size_t)qrow1 * HD + s * 8 + t4]);
            qA[s][2] = __float_as_uint(qb[(size_t)qrow0 * HD + s * 8 + t4 + 4]);
            qA[s][3] = __float_as_uint(qb[(size_t)qrow1 * HD + s * 8 + t4 + 4]);
        }
    }

    float o[4][4];
#pragma unroll
    for (int i = 0; i < 4; i++)
#pragma unroll
        for (int j = 0; j < 4; j++) o[i][j] = 0.f;
    float l0 = 0.f, l1 = 0.f;

    const int qr0i = qrow0 / GW;
    const float qr0 = (float)qr0i, qc0 = (float)(qrow0 - qr0i * GW);
    const int qr1i = qrow1 / GW;
    const float qr1 = (float)qr1i, qc1 = (float)(qrow1 - qr1i * GW);
    const float decay = logf(1.0f - exp2f(-(1.0f + 0.375f * (float)h)));

    const float* kb = g_k + (size_t)bh * NPOS * HD;
    const float* vtb = g_vt + (size_t)bh * HD * NPOS;

    // ---- async tile fill ----
    auto fill = [&](int t, int bb) {
        const uint32_t bu = sbase + (uint32_t)bb * (ABUF * 4);
#pragma unroll
        for (int i = 0; i < 4; i++) {
            int idx = tid + i * 256;
            int row = idx >> 3, c = idx & 7;       // K: 128 rows x 8 float4
            cpa16(bu + (uint32_t)(row * KS_F + c * 4) * 4,
                  kb + ((size_t)t * 128 + row) * HD + c * 4);
        }
#pragma unroll
        for (int i = 0; i < 4; i++) {
            int idx = tid + i * 256;
            int row = idx >> 5, c = idx & 31;      // VT: 32 rows x 32 float4
            cpa16(bu + (uint32_t)(AOFF_VT + row * VT_F + c * 4) * 4,
                  vtb + (size_t)row * NPOS + t * 128 + c * 4);
        }
        if (tid < 128) {
            int kk = t * 128 + tid;
            int kr = kk / GW;
            dyn[bb * ABUF + AOFF_KR + tid] = (float)kr;
            dyn[bb * ABUF + AOFF_KC + tid] = (float)(kk - kr * GW);
        }
        asm volatile("cp.async.commit_group;" ::: "memory");
    };

    fill(0, 0);

    for (int t = 0; t < NPOS / 128; t++) {
        const int bb = t & 1;
        if (t < NPOS / 128 - 1) {
            fill(t + 1, bb ^ 1);
            asm volatile("cp.async.wait_group 1;" ::: "memory");
        } else {
            asm volatile("cp.async.wait_group 0;" ::: "memory");
        }
        __syncthreads();

        const float* ksS = dyn + bb * ABUF;
        const float* vtS = ksS + AOFF_VT;
        const float* krf = ksS + AOFF_KR;
        const float* kcf = ksS + AOFF_KC;

#pragma unroll
        for (int gr = 0; gr < 16; gr++) {
            // ---- QK^T with permuted key columns ----
            float sf[4] = {0.f, 0.f, 0.f, 0.f};
            const float* krow = ksS + (gr * 8 + sg) * KS_F;
#pragma unroll
            for (int s = 0; s < 4; s++) {
                uint32_t b0 = __float_as_uint(krow[s * 8 + t4]);
                uint32_t b1 = __float_as_uint(krow[s * 8 + t4 + 4]);
                mma_tf32(sf, qA[s], b0, b1, sf);
            }
            // C-frag holds physical keys col0 = gr*8+t4, col1 = col0+4
            int col0 = gr * 8 + t4;
            int col1 = col0 + 4;
            float kra = krf[col0], kca = kcf[col0];
            float krb = krf[col1], kcb = kcf[col1];
            float p0 = to_tf32f(__expf(fmaf(decay, fabsf(qr0 - kra) + fabsf(qc0 - kca), sf[0])));
            float p1 = to_tf32f(__expf(fmaf(decay, fabsf(qr0 - krb) + fabsf(qc0 - kcb), sf[1])));
            float p2 = to_tf32f(__expf(fmaf(decay, fabsf(qr1 - kra) + fabsf(qc1 - kca), sf[2])));
            float p3 = to_tf32f(__expf(fmaf(decay, fabsf(qr1 - krb) + fabsf(qc1 - kcb), sf[3])));
            l0 += p0 + p1;
            l1 += p2 + p3;
            uint32_t aP[4];
            aP[0] = __float_as_uint(p0);
            aP[1] = __float_as_uint(p2);
            aP[2] = __float_as_uint(p1);
            aP[3] = __float_as_uint(p3);

            // ---- PV: O[16 x 32] += P[16 x 8keys] @ V[8keys x 32d] ----
#pragma unroll
            for (int nc = 0; nc < 4; nc++) {
                const float* vrow = vtS + (nc * 8 + grp) * VT_F + gr * 8;
                uint32_t b0 = __float_as_uint(vrow[t4]);
                uint32_t b1 = __float_as_uint(vrow[t4 + 4]);
                mma_tf32(o[nc], aP, b0, b1, o[nc]);
            }
        }
        __syncthreads();
    }

    l0 += __shfl_xor_sync(0xFFFFFFFFu, l0, 1);
    l0 += __shfl_xor_sync(0xFFFFFFFFu, l0, 2);
    l1 += __shfl_xor_sync(0xFFFFFFFFu, l1, 1);
    l1 += __shfl_xor_sync(0xFFFFFFFFu, l1, 2);
    const float inv0 = 1.0f / l0;
    const float inv1 = 1.0f / l1;

#pragma unroll
    for (int nc = 0; nc < 4; nc++) {
        int d = h * HD + nc * 8 + t4 * 2;
        float2 w0 = make_float2(o[nc][0] * inv0, o[nc][1] * inv0);
        float2 w1 = make_float2(o[nc][2] * inv1, o[nc][3] * inv1);
        *(float2*)(g_attn + (size_t)(b * NPOS + qrow0) * CDIM + d) = w0;
        *(float2*)(g_attn + (size_t)(b * NPOS + qrow1) * CDIM + d) = w1;
    }
}

// ---------------------------------------------------------------------------
// tf32-mma output GEMM: out = (g_attn + g_lepe) @ Wo + bo
// grid (MTOT/128, CDIM/64)
// ---------------------------------------------------------------------------
__global__ __launch_bounds__(128) void out_mma(
    const float* __restrict__ Wo, const float* __restrict__ bo,
    float* __restrict__ out)
{
    __shared__ __align__(16) float xs[128 * XS];
    __shared__ __align__(16) float ws[32 * WS];

    const int tid = threadIdx.x;
    const int lane = tid & 31, wid = tid >> 5;
    const int grp = lane >> 2, t4 = lane & 3;
    const int mb = blockIdx.x * 128, nb = blockIdx.y * 64;

    float acc[2][8][4];
#pragma unroll
    for (int mi = 0; mi < 2; mi++)
#pragma unroll
        for (int n = 0; n < 8; n++)
#pragma unroll
            for (int j = 0; j < 4; j++) acc[mi][n][j] = 0.f;

    for (int k0 = 0; k0 < CDIM; k0 += 32) {
        __syncthreads();
#pragma unroll
        for (int i = 0; i < 8; i++) {
            int idx = tid + i * 128;
            int row = idx >> 3, c = idx & 7;
            size_t off = (size_t)(mb + row) * CDIM + k0 + c * 4;
            float4 a = *(const float4*)&g_attn[off];
            float4 e = *(const float4*)&g_lepe[off];
            a.x = to_tf32f(a.x + e.x); a.y = to_tf32f(a.y + e.y);
            a.z = to_tf32f(a.z + e.z); a.w = to_tf32f(a.w + e.w);
            *(float4*)(xs + row * XS + c * 4) = a;
        }
#pragma unroll
        for (int i = 0; i < 4; i++) {
            int idx = tid + i * 128;
            int row = idx >> 4, c = idx & 15;
            float4 a = *(const float4*)&Wo[(size_t)(k0 + row) * CDIM + nb + c * 4];
            a.x = to_tf32f(a.x); a.y = to_tf32f(a.y);
            a.z = to_tf32f(a.z); a.w = to_tf32f(a.w);
            *(float4*)(ws + row * WS + c * 4) = a;
        }
        __syncthreads();

#pragma unroll
        for (int ks = 0; ks < 4; ks++) {
            uint32_t bf[8][2];
#pragma unroll
            for (int n = 0; n < 8; n++) {
                bf[n][0] = __float_as_uint(ws[(ks * 8 + t4) * WS + n * 8 + grp]);
                bf[n][1] = __float_as_uint(ws[(ks * 8 + t4 + 4) * WS + n * 8 + grp]);
            }
            uint32_t af[2][4];
#pragma unroll
            for (int mi = 0; mi < 2; mi++) {
                const float* xrow = xs + (wid * 32 + mi * 16 + grp) * XS + ks * 8;
                const float* xrow8 = xrow + 8 * XS;
                af[mi][0] = __float_as_uint(xrow[t4]);
                af[mi][1] = __float_as_uint(xrow8[t4]);
                af[mi][2] = __float_as_uint(xrow[t4 + 4]);
                af[mi][3] = __float_as_uint(xrow8[t4 + 4]);
            }
#pragma unroll
            for (int mi = 0; mi < 2; mi++)
#pragma unroll
                for (int n = 0; n < 8; n++)
                    mma_tf32(acc[mi][n], af[mi], bf[n][0], bf[n][1], acc[mi][n]);
        }
    }

#pragma unroll
    for (int mi = 0; mi < 2; mi++) {
#pragma unroll
        for (int rh = 0; rh < 2; rh++) {
            int row = mb + wid * 32 + mi * 16 + rh * 8 + grp;
#pragma unroll
            for (int n = 0; n < 8; n++) {
                int col = nb + n * 8 + 2 * t4;
                float v0 = acc[mi][n][rh * 2 + 0] + bo[col];
                float v1 = acc[mi][n][rh * 2 + 1] + bo[col + 1];
                *(float2*)&out[(size_t)row * CDIM + col] = make_float2(v0, v1);
            }
        }
    }
}

// ---------------------------------------------------------------------------
extern "C" void kernel_launch(void* const* d_in, const int* in_sizes, int n_in,
                              void* d_out, int out_size)
{
    const float* x      = (const float*)d_in[0];
    const float* Wq     = (const float*)d_in[1];
    const float* bq     = (const float*)d_in[2];
    const float* Wk     = (const float*)d_in[3];
    const float* bk     = (const float*)d_in[4];
    const float* Wv     = (const float*)d_in[5];
    const float* bv     = (const float*)d_in[6];
    const float* lepe_w = (const float*)d_in[7];
    const float* lepe_b = (const float*)d_in[8];
    const float* Wo     = (const float*)d_in[9];
    const float* bo     = (const float*)d_in[10];
    float* out = (float*)d_out;

    rotary_table<<<(NPOS * 16 + 255) / 256, 256>>>();
    transpose_w<<<(25 * CDIM + 255) / 256, 256>>>(lepe_w);

    dim3 g1(MTOT / 128, CDIM / 64, 3);
    qkv_mma<<<g1, 128>>>(x, Wq, bq, Wk, bk, Wv, bv);

    dim3 gv(NPOS / 32, BH);
    vt_kernel<<<gv, dim3(32, 8)>>>();

    dwconv<<<MTOT, 256>>>(lepe_b);

    const int attn_smem = 2 * ABUF * 4;   // 72704 B
    cudaFuncSetAttribute(attn_pipe, cudaFuncAttributeMaxDynamicSharedMemorySize, attn_smem);
    dim3 g3(NPOS / 128, BH);
    attn_pipe<<<g3, 256, attn_smem>>>();

    dim3 g4(MTOT / 128, CDIM / 64);
    out_mma<<<g4, 128>>>(Wo, bo, out);
}

// round 13
// speedup vs baseline: 6.2435x; 1.0849x over previous
#include <cuda_runtime.h>
#include <math.h>
#include <cstdint>

#define HEADS 8
#define HD 32
#define NPOS 2304
#define GW 48
#define CDIM 256
#define BATCH 2
#define MTOT (BATCH*NPOS)   // 4608
#define BH (BATCH*HEADS)    // 16

// Scratch (static device arrays; no allocation allowed)
__device__ float g_v[BATCH*HEADS*NPOS*HD];    // [bh][n][d] fp32 (dwconv, vt source)
__device__ float g_q[BATCH*HEADS*NPOS*HD];    // [bh][n][d] rotary q, tf32-rounded
__device__ float g_k[BATCH*HEADS*NPOS*HD];    // [bh][n][d] rotary scaled k, tf32-rounded
__device__ float g_vt[BATCH*HEADS*HD*NPOS];   // [bh][d][n] V transposed, tf32-rounded
__device__ float g_lepe[BATCH*NPOS*CDIM];
__device__ float g_attn[BATCH*NPOS*CDIM];
__device__ float g_wt[25*CDIM];
__device__ float g_sin[NPOS*16];
__device__ float g_cos[NPOS*16];

// ---- tf32 helpers ----------------------------------------------------------
__device__ __forceinline__ uint32_t to_tf32(float f)
{
    uint32_t r;
    asm("cvt.rna.tf32.f32 %0, %1;" : "=r"(r) : "f"(f));
    return r;
}
__device__ __forceinline__ float to_tf32f(float f)
{
    return __uint_as_float(to_tf32(f));
}
__device__ __forceinline__ void mma_tf32(
    float* d, const uint32_t* a, uint32_t b0, uint32_t b1, const float* c)
{
    asm volatile(
        "mma.sync.aligned.m16n8k8.row.col.f32.tf32.tf32.f32 "
        "{%0,%1,%2,%3}, {%4,%5,%6,%7}, {%8,%9}, {%10,%11,%12,%13};"
        : "=f"(d[0]), "=f"(d[1]), "=f"(d[2]), "=f"(d[3])
        : "r"(a[0]), "r"(a[1]), "r"(a[2]), "r"(a[3]),
          "r"(b0), "r"(b1),
          "f"(c[0]), "f"(c[1]), "f"(c[2]), "f"(c[3]));
}
__device__ __forceinline__ uint32_t smem_u32(const void* p)
{
    uint32_t a;
    asm("{ .reg .u64 t; cvta.to.shared.u64 t, %1; cvt.u32.u64 %0, t; }" : "=r"(a) : "l"(p));
    return a;
}
__device__ __forceinline__ void cpa16(uint32_t saddr, const void* g)
{
    asm volatile("cp.async.cg.shared.global [%0], [%1], 16;" :: "r"(saddr), "l"(g));
}

// ---------------------------------------------------------------------------
// Setup: rotary sin/cos table + depthwise weight transpose (one kernel)
// ---------------------------------------------------------------------------
__global__ void setup_tables(const float* __restrict__ lw)
{
    int t = blockIdx.x * 256 + threadIdx.x;
    if (t < NPOS * 16) {
        int pos = t >> 4, pj = t & 15;
        float ang = expf(-(float)pj * (9.210340371976184f / 15.0f));
        float s, c;
        sincosf((float)pos * ang, &s, &c);
        g_sin[t] = s;
        g_cos[t] = c;
    } else {
        int u = t - NPOS * 16;
        if (u < 25 * CDIM) {
            int ch = u / 25, tap = u - ch * 25;
            g_wt[tap * CDIM + ch] = lw[u];
        }
    }
}

// ---------------------------------------------------------------------------
// tf32-mma QKV GEMM: y = x @ W + b; 128 threads, BM=128, BN=64, BK=32.
// grid (MTOT/128, CDIM/64, 3)
// ---------------------------------------------------------------------------
#define XS 36
#define WS 72

__global__ __launch_bounds__(128) void qkv_mma(
    const float* __restrict__ x,
    const float* __restrict__ Wq, const float* __restrict__ bq,
    const float* __restrict__ Wk, const float* __restrict__ bk,
    const float* __restrict__ Wv, const float* __restrict__ bv)
{
    const int which = blockIdx.z;
    const float* __restrict__ W    = (which == 0) ? Wq : (which == 1 ? Wk : Wv);
    const float* __restrict__ bias = (which == 0) ? bq : (which == 1 ? bk : bv);

    __shared__ __align__(16) float xs[128 * XS];
    __shared__ __align__(16) float ws[32 * WS];

    const int tid = threadIdx.x;
    const int lane = tid & 31, wid = tid >> 5;
    const int grp = lane >> 2, t4 = lane & 3;
    const int mb = blockIdx.x * 128, nb = blockIdx.y * 64;

    float acc[2][8][4];
#pragma unroll
    for (int mi = 0; mi < 2; mi++)
#pragma unroll
        for (int n = 0; n < 8; n++)
#pragma unroll
            for (int j = 0; j < 4; j++) acc[mi][n][j] = 0.f;

    for (int k0 = 0; k0 < CDIM; k0 += 32) {
        __syncthreads();
#pragma unroll
        for (int i = 0; i < 8; i++) {
            int idx = tid + i * 128;
            int row = idx >> 3, c = idx & 7;
            float4 a = *(const float4*)&x[(size_t)(mb + row) * CDIM + k0 + c * 4];
            a.x = to_tf32f(a.x); a.y = to_tf32f(a.y);
            a.z = to_tf32f(a.z); a.w = to_tf32f(a.w);
            *(float4*)(xs + row * XS + c * 4) = a;
        }
#pragma unroll
        for (int i = 0; i < 4; i++) {
            int idx = tid + i * 128;
            int row = idx >> 4, c = idx & 15;
            float4 a = *(const float4*)&W[(size_t)(k0 + row) * CDIM + nb + c * 4];
            a.x = to_tf32f(a.x); a.y = to_tf32f(a.y);
            a.z = to_tf32f(a.z); a.w = to_tf32f(a.w);
            *(float4*)(ws + row * WS + c * 4) = a;
        }
        __syncthreads();

#pragma unroll
        for (int ks = 0; ks < 4; ks++) {
            uint32_t bf[8][2];
#pragma unroll
            for (int n = 0; n < 8; n++) {
                bf[n][0] = __float_as_uint(ws[(ks * 8 + t4) * WS + n * 8 + grp]);
                bf[n][1] = __float_as_uint(ws[(ks * 8 + t4 + 4) * WS + n * 8 + grp]);
            }
            uint32_t af[2][4];
#pragma unroll
            for (int mi = 0; mi < 2; mi++) {
                const float* xrow = xs + (wid * 32 + mi * 16 + grp) * XS + ks * 8;
                const float* xrow8 = xrow + 8 * XS;
                af[mi][0] = __float_as_uint(xrow[t4]);
                af[mi][1] = __float_as_uint(xrow8[t4]);
                af[mi][2] = __float_as_uint(xrow[t4 + 4]);
                af[mi][3] = __float_as_uint(xrow8[t4 + 4]);
            }
#pragma unroll
            for (int mi = 0; mi < 2; mi++)
#pragma unroll
                for (int n = 0; n < 8; n++)
                    mma_tf32(acc[mi][n], af[mi], bf[n][0], bf[n][1], acc[mi][n]);
        }
    }

    const float scal = (which == 1) ? 0.17677669529663687f : 1.0f;

#pragma unroll
    for (int mi = 0; mi < 2; mi++) {
#pragma unroll
        for (int rh = 0; rh < 2; rh++) {
            int row = mb + wid * 32 + mi * 16 + rh * 8 + grp;
            int b = (row >= NPOS) ? 1 : 0;
            int pos = row - b * NPOS;
#pragma unroll
            for (int n = 0; n < 8; n++) {
                int col = nb + n * 8 + 2 * t4;
                float v0 = acc[mi][n][rh * 2 + 0] + bias[col];
                float v1 = acc[mi][n][rh * 2 + 1] + bias[col + 1];
                size_t base = (((size_t)(b * HEADS + (col >> 5))) * NPOS + pos) * HD + (col & 31);
                if (which == 2) {
                    *(float2*)&g_v[base] = make_float2(v0, v1);
                } else {
                    int pj = (col & 31) >> 1;
                    float s = g_sin[pos * 16 + pj];
                    float c = g_cos[pos * 16 + pj];
                    v0 *= scal; v1 *= scal;
                    float* dst = (which == 0) ? g_q : g_k;
                    *(float2*)&dst[base] =
                        make_float2(to_tf32f(v0 * c - v1 * s), to_tf32f(v1 * c + v0 * s));
                }
            }
        }
    }
}

// ---------------------------------------------------------------------------
// Transpose V: [bh][n][d] fp32 -> [bh][d][n] tf32-rounded fp32
// ---------------------------------------------------------------------------
__global__ __launch_bounds__(256) void vt_kernel()
{
    __shared__ float tile[32][33];
    const int bh = blockIdx.y;
    const int p0 = blockIdx.x * 32;
    const int tx = threadIdx.x, ty = threadIdx.y;
#pragma unroll
    for (int i = 0; i < 4; i++) {
        int row = ty + i * 8;
        tile[row][tx] = g_v[((size_t)bh * NPOS + p0 + row) * HD + tx];
    }
    __syncthreads();
#pragma unroll
    for (int i = 0; i < 4; i++) {
        int d = ty + i * 8;
        g_vt[((size_t)bh * HD + d) * NPOS + p0 + tx] = to_tf32f(tile[tx][d]);
    }
}

// ---------------------------------------------------------------------------
// Depthwise 5x5 conv, 4 outputs/thread (rows r0..r0+3, one col, one channel).
// Weights hoisted to registers (25), input rows streamed (8 rows x 5 cols).
// grid = MTOT*CDIM/4/256 = 1152 blocks.
// ---------------------------------------------------------------------------
__global__ __launch_bounds__(256) void dwconv(const float* __restrict__ lepe_b)
{
    int t = blockIdx.x * 256 + threadIdx.x;
    int ch = t & 255;
    int sp = t >> 8;                 // 0..1151 : b(2) x rowgroup(12) x col(48)
    int b = sp / 576;
    int rem = sp - b * 576;
    int rg = rem / 48;
    int c = rem - rg * 48;
    int r0 = rg * 4;

    const float* vb = g_v + ((size_t)(b * HEADS + (ch >> 5)) * NPOS) * HD + (ch & 31);

    float w[25];
#pragma unroll
    for (int i = 0; i < 25; i++) w[i] = g_wt[i * CDIM + ch];

    float bsv = lepe_b[ch];
    float s[4] = {bsv, bsv, bsv, bsv};

#pragma unroll
    for (int dri = 0; dri < 8; dri++) {
        const int dr = dri - 2;            // row offset from r0: -2..5
        int rr = r0 + dr;
        if ((unsigned)rr < GW) {
            float vin[5];
#pragma unroll
            for (int jj = 0; jj < 5; jj++) {
                int cc = c + jj - 2;
                vin[jj] = ((unsigned)cc < GW) ? vb[(size_t)(rr * GW + cc) * HD] : 0.f;
            }
            const int jlo = (dr - 2 > 0) ? dr - 2 : 0;
            const int jhi = (dr + 2 < 3) ? dr + 2 : 3;
#pragma unroll
            for (int j = jlo; j <= jhi; j++) {
                const int wi = (dr - j + 2) * 5;
                s[j] += vin[0] * w[wi + 0] + vin[1] * w[wi + 1] + vin[2] * w[wi + 2]
                      + vin[3] * w[wi + 3] + vin[4] * w[wi + 4];
            }
        }
    }

#pragma unroll
    for (int j = 0; j < 4; j++) {
        g_lepe[((size_t)(b * NPOS + (r0 + j) * GW + c)) * CDIM + ch] = s[j];
    }
}

// ---------------------------------------------------------------------------
// Flash attention: tf32 mma, shuffle-free (key-permutation), 256 threads,
// 256 queries/block (32 rows/warp = 2 m-fragments), double-buffered cp.async.
// grid (NPOS/256 = 9, BH). Buffer: ks[128*36] | vt[32*132] | krf[128] | kcf[128]
// ---------------------------------------------------------------------------
#define KS_F 36
#define VT_F 132
#define ABUF 9088
#define AOFF_VT 4608
#define AOFF_KR 8832
#define AOFF_KC 8960

__global__ __launch_bounds__(256) void attn_pipe()
{
    extern __shared__ __align__(16) float dyn[];
    const uint32_t sbase = smem_u32(dyn);

    const int tid = threadIdx.x;
    const int lane = tid & 31, wid = tid >> 5;
    const int grp = lane >> 2, t4 = lane & 3;
    const int sg = (grp >> 1) + ((grp & 1) << 2);   // sigma(grp)
    const int bh = blockIdx.y, h = bh & 7, b = bh >> 3;
    const int q0 = blockIdx.x * 256;
    const int rowA = q0 + wid * 32 + grp;           // mi*16 + rh*8 offsets apply

    // Q fragments: 2 m-tiles x 4 k-steps
    uint32_t qA[2][4][4];
    {
        const float* qb = g_q + (size_t)bh * NPOS * HD;
#pragma unroll
        for (int mi = 0; mi < 2; mi++)
#pragma unroll
            for (int s = 0; s < 4; s++) {
                const float* r0p = qb + (size_t)(rowA + mi * 16) * HD + s * 8;
                const float* r8p = r0p + 8 * HD;
                qA[mi][s][0] = __float_as_uint(r0p[t4]);
                qA[mi][s][1] = __float_as_uint(r8p[t4]);
                qA[mi][s][2] = __float_as_uint(r0p[t4 + 4]);
                qA[mi][s][3] = __float_as_uint(r8p[t4 + 4]);
            }
    }

    float o[2][4][4];
#pragma unroll
    for (int mi = 0; mi < 2; mi++)
#pragma unroll
        for (int i = 0; i < 4; i++)
#pragma unroll
            for (int j = 0; j < 4; j++) o[mi][i][j] = 0.f;
    float lA[2] = {0.f, 0.f}, lB[2] = {0.f, 0.f};

    float qrF[2][2], qcF[2][2];
#pragma unroll
    for (int mi = 0; mi < 2; mi++)
#pragma unroll
        for (int rh = 0; rh < 2; rh++) {
            int qr_ = rowA + mi * 16 + rh * 8;
            int qri = qr_ / GW;
            qrF[mi][rh] = (float)qri;
            qcF[mi][rh] = (float)(qr_ - qri * GW);
        }
    const float decay = logf(1.0f - exp2f(-(1.0f + 0.375f * (float)h)));

    const float* kb = g_k + (size_t)bh * NPOS * HD;
    const float* vtb = g_vt + (size_t)bh * HD * NPOS;

    auto fill = [&](int t, int bb) {
        const uint32_t bu = sbase + (uint32_t)bb * (ABUF * 4);
#pragma unroll
        for (int i = 0; i < 4; i++) {
            int idx = tid + i * 256;
            int row = idx >> 3, c = idx & 7;       // K: 128 rows x 8 float4
            cpa16(bu + (uint32_t)(row * KS_F + c * 4) * 4,
                  kb + ((size_t)t * 128 + row) * HD + c * 4);
        }
#pragma unroll
        for (int i = 0; i < 4; i++) {
            int idx = tid + i * 256;
            int row = idx >> 5, c = idx & 31;      // VT: 32 rows x 32 float4
            cpa16(bu + (uint32_t)(AOFF_VT + row * VT_F + c * 4) * 4,
                  vtb + (size_t)row * NPOS + t * 128 + c * 4);
        }
        if (tid < 128) {
            int kk = t * 128 + tid;
            int kr = kk / GW;
            dyn[bb * ABUF + AOFF_KR + tid] = (float)kr;
            dyn[bb * ABUF + AOFF_KC + tid] = (float)(kk - kr * GW);
        }
        asm volatile("cp.async.commit_group;" ::: "memory");
    };

    fill(0, 0);

    for (int t = 0; t < NPOS / 128; t++) {
        const int bb = t & 1;
        if (t < NPOS / 128 - 1) {
            fill(t + 1, bb ^ 1);
            asm volatile("cp.async.wait_group 1;" ::: "memory");
        } else {
            asm volatile("cp.async.wait_group 0;" ::: "memory");
        }
        __syncthreads();

        const float* ksS = dyn + bb * ABUF;
        const float* vtS = ksS + AOFF_VT;
        const float* krf = ksS + AOFF_KR;
        const float* kcf = ksS + AOFF_KC;

#pragma unroll
        for (int gr = 0; gr < 16; gr++) {
            // ---- QK^T B-fragments once, shared across both m-tiles ----
            const float* krow = ksS + (gr * 8 + sg) * KS_F;
            uint32_t kb0[4], kb1[4];
#pragma unroll
            for (int s = 0; s < 4; s++) {
                kb0[s] = __float_as_uint(krow[s * 8 + t4]);
                kb1[s] = __float_as_uint(krow[s * 8 + t4 + 4]);
            }
            float sf[2][4];
#pragma unroll
            for (int mi = 0; mi < 2; mi++) {
                sf[mi][0] = sf[mi][1] = sf[mi][2] = sf[mi][3] = 0.f;
#pragma unroll
                for (int s = 0; s < 4; s++)
                    mma_tf32(sf[mi], qA[mi][s], kb0[s], kb1[s], sf[mi]);
            }
            // C-frag holds physical keys col0 = gr*8+t4, col1 = col0+4
            int col0 = gr * 8 + t4;
            int col1 = col0 + 4;
            float kra = krf[col0], kca = kcf[col0];
            float krb = krf[col1], kcb = kcf[col1];

            uint32_t aP[2][4];
#pragma unroll
            for (int mi = 0; mi < 2; mi++) {
                float p0 = to_tf32f(__expf(fmaf(decay,
                    fabsf(qrF[mi][0] - kra) + fabsf(qcF[mi][0] - kca), sf[mi][0])));
                float p1 = to_tf32f(__expf(fmaf(decay,
                    fabsf(qrF[mi][0] - krb) + fabsf(qcF[mi][0] - kcb), sf[mi][1])));
                float p2 = to_tf32f(__expf(fmaf(decay,
                    fabsf(qrF[mi][1] - kra) + fabsf(qcF[mi][1] - kca), sf[mi][2])));
                float p3 = to_tf32f(__expf(fmaf(decay,
                    fabsf(qrF[mi][1] - krb) + fabsf(qcF[mi][1] - kcb), sf[mi][3])));
                lA[mi] += p0 + p1;
                lB[mi] += p2 + p3;
                aP[mi][0] = __float_as_uint(p0);
                aP[mi][1] = __float_as_uint(p2);
                aP[mi][2] = __float_as_uint(p1);
                aP[mi][3] = __float_as_uint(p3);
            }

            // ---- PV B-fragments once, shared across both m-tiles ----
#pragma unroll
            for (int nc = 0; nc < 4; nc++) {
                const float* vrow = vtS + (nc * 8 + grp) * VT_F + gr * 8;
                uint32_t b0 = __float_as_uint(vrow[t4]);
                uint32_t b1 = __float_as_uint(vrow[t4 + 4]);
#pragma unroll
                for (int mi = 0; mi < 2; mi++)
                    mma_tf32(o[mi][nc], aP[mi], b0, b1, o[mi][nc]);
            }
        }
        __syncthreads();
    }

#pragma unroll
    for (int mi = 0; mi < 2; mi++) {
        lA[mi] += __shfl_xor_sync(0xFFFFFFFFu, lA[mi], 1);
        lA[mi] += __shfl_xor_sync(0xFFFFFFFFu, lA[mi], 2);
        lB[mi] += __shfl_xor_sync(0xFFFFFFFFu, lB[mi], 1);
        lB[mi] += __shfl_xor_sync(0xFFFFFFFFu, lB[mi], 2);
    }

#pragma unroll
    for (int mi = 0; mi < 2; mi++) {
        const float invA = 1.0f / lA[mi];
        const float invB = 1.0f / lB[mi];
        const int r0 = rowA + mi * 16;
#pragma unroll
        for (int nc = 0; nc < 4; nc++) {
            int d = h * HD + nc * 8 + t4 * 2;
            float2 w0 = make_float2(o[mi][nc][0] * invA, o[mi][nc][1] * invA);
            float2 w1 = make_float2(o[mi][nc][2] * invB, o[mi][nc][3] * invB);
            *(float2*)(g_attn + (size_t)(b * NPOS + r0) * CDIM + d) = w0;
            *(float2*)(g_attn + (size_t)(b * NPOS + r0 + 8) * CDIM + d) = w1;
        }
    }
}

// ---------------------------------------------------------------------------
// tf32-mma output GEMM: out = (g_attn + g_lepe) @ Wo + bo
// grid (MTOT/128, CDIM/64)
// ---------------------------------------------------------------------------
__global__ __launch_bounds__(128) void out_mma(
    const float* __restrict__ Wo, const float* __restrict__ bo,
    float* __restrict__ out)
{
    __shared__ __align__(16) float xs[128 * XS];
    __shared__ __align__(16) float ws[32 * WS];

    const int tid = threadIdx.x;
    const int lane = tid & 31, wid = tid >> 5;
    const int grp = lane >> 2, t4 = lane & 3;
    const int mb = blockIdx.x * 128, nb = blockIdx.y * 64;

    float acc[2][8][4];
#pragma unroll
    for (int mi = 0; mi < 2; mi++)
#pragma unroll
        for (int n = 0; n < 8; n++)
#pragma unroll
            for (int j = 0; j < 4; j++) acc[mi][n][j] = 0.f;

    for (int k0 = 0; k0 < CDIM; k0 += 32) {
        __syncthreads();
#pragma unroll
        for (int i = 0; i < 8; i++) {
            int idx = tid + i * 128;
            int row = idx >> 3, c = idx & 7;
            size_t off = (size_t)(mb + row) * CDIM + k0 + c * 4;
            float4 a = *(const float4*)&g_attn[off];
            float4 e = *(const float4*)&g_lepe[off];
            a.x = to_tf32f(a.x + e.x); a.y = to_tf32f(a.y + e.y);
            a.z = to_tf32f(a.z + e.z); a.w = to_tf32f(a.w + e.w);
            *(float4*)(xs + row * XS + c * 4) = a;
        }
#pragma unroll
        for (int i = 0; i < 4; i++) {
            int idx = tid + i * 128;
            int row = idx >> 4, c = idx & 15;
            float4 a = *(const float4*)&Wo[(size_t)(k0 + row) * CDIM + nb + c * 4];
            a.x = to_tf32f(a.x); a.y = to_tf32f(a.y);
            a.z = to_tf32f(a.z); a.w = to_tf32f(a.w);
            *(float4*)(ws + row * WS + c * 4) = a;
        }
        __syncthreads();

#pragma unroll
        for (int ks = 0; ks < 4; ks++) {
            uint32_t bf[8][2];
#pragma unroll
            for (int n = 0; n < 8; n++) {
                bf[n][0] = __float_as_uint(ws[(ks * 8 + t4) * WS + n * 8 + grp]);
                bf[n][1] = __float_as_uint(ws[(ks * 8 + t4 + 4) * WS + n * 8 + grp]);
            }
            uint32_t af[2][4];
#pragma unroll
            for (int mi = 0; mi < 2; mi++) {
                const float* xrow = xs + (wid * 32 + mi * 16 + grp) * XS + ks * 8;
                const float* xrow8 = xrow + 8 * XS;
                af[mi][0] = __float_as_uint(xrow[t4]);
                af[mi][1] = __float_as_uint(xrow8[t4]);
                af[mi][2] = __float_as_uint(xrow[t4 + 4]);
                af[mi][3] = __float_as_uint(xrow8[t4 + 4]);
            }
#pragma unroll
            for (int mi = 0; mi < 2; mi++)
#pragma unroll
                for (int n = 0; n < 8; n++)
                    mma_tf32(acc[mi][n], af[mi], bf[n][0], bf[n][1], acc[mi][n]);
        }
    }

#pragma unroll
    for (int mi = 0; mi < 2; mi++) {
#pragma unroll
        for (int rh = 0; rh < 2; rh++) {
            int row = mb + wid * 32 + mi * 16 + rh * 8 + grp;
#pragma unroll
            for (int n = 0; n < 8; n++) {
                int col = nb + n * 8 + 2 * t4;
                float v0 = acc[mi][n][rh * 2 + 0] + bo[col];
                float v1 = acc[mi][n][rh * 2 + 1] + bo[col + 1];
                *(float2*)&out[(size_t)row * CDIM + col] = make_float2(v0, v1);
            }
        }
    }
}

// ---------------------------------------------------------------------------
extern "C" void kernel_launch(void* const* d_in, const int* in_sizes, int n_in,
                              void* d_out, int out_size)
{
    const float* x      = (const float*)d_in[0];
    const float* Wq     = (const float*)d_in[1];
    const float* bq     = (const float*)d_in[2];
    const float* Wk     = (const float*)d_in[3];
    const float* bk     = (const float*)d_in[4];
    const float* Wv     = (const float*)d_in[5];
    const float* bv     = (const float*)d_in[6];
    const float* lepe_w = (const float*)d_in[7];
    const float* lepe_b = (const float*)d_in[8];
    const float* Wo     = (const float*)d_in[9];
    const float* bo     = (const float*)d_in[10];
    float* out = (float*)d_out;

    setup_tables<<<(NPOS * 16 + 25 * CDIM + 255) / 256, 256>>>(lepe_w);

    dim3 g1(MTOT / 128, CDIM / 64, 3);
    qkv_mma<<<g1, 128>>>(x, Wq, bq, Wk, bk, Wv, bv);

    dim3 gv(NPOS / 32, BH);
    vt_kernel<<<gv, dim3(32, 8)>>>();

    dwconv<<<(MTOT * CDIM / 4) / 256, 256>>>(lepe_b);

    const int attn_smem = 2 * ABUF * 4;   // 72704 B
    cudaFuncSetAttribute(attn_pipe, cudaFuncAttributeMaxDynamicSharedMemorySize, attn_smem);
    dim3 g3(NPOS / 256, BH);
    attn_pipe<<<g3, 256, attn_smem>>>();

    dim3 g4(MTOT / 128, CDIM / 64);
    out_mma<<<g4, 128>>>(Wo, bo, out);
}

// round 14
// speedup vs baseline: 6.5242x; 1.0450x over previous
#include <cuda_runtime.h>
#include <math.h>
#include <cstdint>

#define HEADS 8
#define HD 32
#define NPOS 2304
#define GW 48
#define CDIM 256
#define BATCH 2
#define MTOT (BATCH*NPOS)   // 4608
#define BH (BATCH*HEADS)    // 16

// Scratch (static device arrays; no allocation allowed)
__device__ float g_v[BATCH*HEADS*NPOS*HD];    // [bh][n][d] fp32 (dwconv, vt source)
__device__ float g_q[BATCH*HEADS*NPOS*HD];    // [bh][n][d] rotary q, tf32-rounded
__device__ float g_k[BATCH*HEADS*NPOS*HD];    // [bh][n][d] rotary scaled k, tf32-rounded
__device__ float g_vt[BATCH*HEADS*HD*NPOS];   // [bh][d][n] V transposed, tf32-rounded
__device__ float g_lepe[BATCH*NPOS*CDIM];
__device__ float g_attn[BATCH*NPOS*CDIM];
__device__ float g_wt[25*CDIM];
__device__ float g_sin[NPOS*16];
__device__ float g_cos[NPOS*16];
// split-K partials
__device__ float g_part[2*BH*NPOS*HD];
__device__ float g_partl[2*BH*NPOS];

// ---- tf32 helpers ----------------------------------------------------------
__device__ __forceinline__ uint32_t to_tf32(float f)
{
    uint32_t r;
    asm("cvt.rna.tf32.f32 %0, %1;" : "=r"(r) : "f"(f));
    return r;
}
__device__ __forceinline__ float to_tf32f(float f)
{
    return __uint_as_float(to_tf32(f));
}
__device__ __forceinline__ void mma_tf32(
    float* d, const uint32_t* a, uint32_t b0, uint32_t b1, const float* c)
{
    asm volatile(
        "mma.sync.aligned.m16n8k8.row.col.f32.tf32.tf32.f32 "
        "{%0,%1,%2,%3}, {%4,%5,%6,%7}, {%8,%9}, {%10,%11,%12,%13};"
        : "=f"(d[0]), "=f"(d[1]), "=f"(d[2]), "=f"(d[3])
        : "r"(a[0]), "r"(a[1]), "r"(a[2]), "r"(a[3]),
          "r"(b0), "r"(b1),
          "f"(c[0]), "f"(c[1]), "f"(c[2]), "f"(c[3]));
}
__device__ __forceinline__ uint32_t smem_u32(const void* p)
{
    uint32_t a;
    asm("{ .reg .u64 t; cvta.to.shared.u64 t, %1; cvt.u32.u64 %0, t; }" : "=r"(a) : "l"(p));
    return a;
}
__device__ __forceinline__ void cpa16(uint32_t saddr, const void* g)
{
    asm volatile("cp.async.cg.shared.global [%0], [%1], 16;" :: "r"(saddr), "l"(g));
}

// ---------------------------------------------------------------------------
// Setup: rotary sin/cos table + depthwise weight transpose (one kernel)
// ---------------------------------------------------------------------------
__global__ void setup_tables(const float* __restrict__ lw)
{
    int t = blockIdx.x * 256 + threadIdx.x;
    if (t < NPOS * 16) {
        int pos = t >> 4, pj = t & 15;
        float ang = expf(-(float)pj * (9.210340371976184f / 15.0f));
        float s, c;
        sincosf((float)pos * ang, &s, &c);
        g_sin[t] = s;
        g_cos[t] = c;
    } else {
        int u = t - NPOS * 16;
        if (u < 25 * CDIM) {
            int ch = u / 25, tap = u - ch * 25;
            g_wt[tap * CDIM + ch] = lw[u];
        }
    }
}

// ---------------------------------------------------------------------------
// tf32-mma QKV GEMM: y = x @ W + b; 128 threads, BM=128, BN=64, BK=32.
// grid (MTOT/128, CDIM/64, 3)
// ---------------------------------------------------------------------------
#define XS 36
#define WS 72

__global__ __launch_bounds__(128) void qkv_mma(
    const float* __restrict__ x,
    const float* __restrict__ Wq, const float* __restrict__ bq,
    const float* __restrict__ Wk, const float* __restrict__ bk,
    const float* __restrict__ Wv, const float* __restrict__ bv)
{
    const int which = blockIdx.z;
    const float* __restrict__ W    = (which == 0) ? Wq : (which == 1 ? Wk : Wv);
    const float* __restrict__ bias = (which == 0) ? bq : (which == 1 ? bk : bv);

    __shared__ __align__(16) float xs[128 * XS];
    __shared__ __align__(16) float ws[32 * WS];

    const int tid = threadIdx.x;
    const int lane = tid & 31, wid = tid >> 5;
    const int grp = lane >> 2, t4 = lane & 3;
    const int mb = blockIdx.x * 128, nb = blockIdx.y * 64;

    float acc[2][8][4];
#pragma unroll
    for (int mi = 0; mi < 2; mi++)
#pragma unroll
        for (int n = 0; n < 8; n++)
#pragma unroll
            for (int j = 0; j < 4; j++) acc[mi][n][j] = 0.f;

    for (int k0 = 0; k0 < CDIM; k0 += 32) {
        __syncthreads();
#pragma unroll
        for (int i = 0; i < 8; i++) {
            int idx = tid + i * 128;
            int row = idx >> 3, c = idx & 7;
            float4 a = *(const float4*)&x[(size_t)(mb + row) * CDIM + k0 + c * 4];
            a.x = to_tf32f(a.x); a.y = to_tf32f(a.y);
            a.z = to_tf32f(a.z); a.w = to_tf32f(a.w);
            *(float4*)(xs + row * XS + c * 4) = a;
        }
#pragma unroll
        for (int i = 0; i < 4; i++) {
            int idx = tid + i * 128;
            int row = idx >> 4, c = idx & 15;
            float4 a = *(const float4*)&W[(size_t)(k0 + row) * CDIM + nb + c * 4];
            a.x = to_tf32f(a.x); a.y = to_tf32f(a.y);
            a.z = to_tf32f(a.z); a.w = to_tf32f(a.w);
            *(float4*)(ws + row * WS + c * 4) = a;
        }
        __syncthreads();

#pragma unroll
        for (int ks = 0; ks < 4; ks++) {
            uint32_t bf[8][2];
#pragma unroll
            for (int n = 0; n < 8; n++) {
                bf[n][0] = __float_as_uint(ws[(ks * 8 + t4) * WS + n * 8 + grp]);
                bf[n][1] = __float_as_uint(ws[(ks * 8 + t4 + 4) * WS + n * 8 + grp]);
            }
            uint32_t af[2][4];
#pragma unroll
            for (int mi = 0; mi < 2; mi++) {
                const float* xrow = xs + (wid * 32 + mi * 16 + grp) * XS + ks * 8;
                const float* xrow8 = xrow + 8 * XS;
                af[mi][0] = __float_as_uint(xrow[t4]);
                af[mi][1] = __float_as_uint(xrow8[t4]);
                af[mi][2] = __float_as_uint(xrow[t4 + 4]);
                af[mi][3] = __float_as_uint(xrow8[t4 + 4]);
            }
#pragma unroll
            for (int mi = 0; mi < 2; mi++)
#pragma unroll
                for (int n = 0; n < 8; n++)
                    mma_tf32(acc[mi][n], af[mi], bf[n][0], bf[n][1], acc[mi][n]);
        }
    }

    const float scal = (which == 1) ? 0.17677669529663687f : 1.0f;

#pragma unroll
    for (int mi = 0; mi < 2; mi++) {
#pragma unroll
        for (int rh = 0; rh < 2; rh++) {
            int row = mb + wid * 32 + mi * 16 + rh * 8 + grp;
            int b = (row >= NPOS) ? 1 : 0;
            int pos = row - b * NPOS;
#pragma unroll
            for (int n = 0; n < 8; n++) {
                int col = nb + n * 8 + 2 * t4;
                float v0 = acc[mi][n][rh * 2 + 0] + bias[col];
                float v1 = acc[mi][n][rh * 2 + 1] + bias[col + 1];
                size_t base = (((size_t)(b * HEADS + (col >> 5))) * NPOS + pos) * HD + (col & 31);
                if (which == 2) {
                    *(float2*)&g_v[base] = make_float2(v0, v1);
                } else {
                    int pj = (col & 31) >> 1;
                    float s = g_sin[pos * 16 + pj];
                    float c = g_cos[pos * 16 + pj];
                    v0 *= scal; v1 *= scal;
                    float* dst = (which == 0) ? g_q : g_k;
                    *(float2*)&dst[base] =
                        make_float2(to_tf32f(v0 * c - v1 * s), to_tf32f(v1 * c + v0 * s));
                }
            }
        }
    }
}

// ---------------------------------------------------------------------------
// Transpose V: [bh][n][d] fp32 -> [bh][d][n] tf32-rounded fp32
// ---------------------------------------------------------------------------
__global__ __launch_bounds__(256) void vt_kernel()
{
    __shared__ float tile[32][33];
    const int bh = blockIdx.y;
    const int p0 = blockIdx.x * 32;
    const int tx = threadIdx.x, ty = threadIdx.y;
#pragma unroll
    for (int i = 0; i < 4; i++) {
        int row = ty + i * 8;
        tile[row][tx] = g_v[((size_t)bh * NPOS + p0 + row) * HD + tx];
    }
    __syncthreads();
#pragma unroll
    for (int i = 0; i < 4; i++) {
        int d = ty + i * 8;
        g_vt[((size_t)bh * HD + d) * NPOS + p0 + tx] = to_tf32f(tile[tx][d]);
    }
}

// ---------------------------------------------------------------------------
// Depthwise 5x5 conv, 4 outputs/thread.
// ---------------------------------------------------------------------------
__global__ __launch_bounds__(256) void dwconv(const float* __restrict__ lepe_b)
{
    int t = blockIdx.x * 256 + threadIdx.x;
    int ch = t & 255;
    int sp = t >> 8;
    int b = sp / 576;
    int rem = sp - b * 576;
    int rg = rem / 48;
    int c = rem - rg * 48;
    int r0 = rg * 4;

    const float* vb = g_v + ((size_t)(b * HEADS + (ch >> 5)) * NPOS) * HD + (ch & 31);

    float w[25];
#pragma unroll
    for (int i = 0; i < 25; i++) w[i] = g_wt[i * CDIM + ch];

    float bsv = lepe_b[ch];
    float s[4] = {bsv, bsv, bsv, bsv};

#pragma unroll
    for (int dri = 0; dri < 8; dri++) {
        const int dr = dri - 2;
        int rr = r0 + dr;
        if ((unsigned)rr < GW) {
            float vin[5];
#pragma unroll
            for (int jj = 0; jj < 5; jj++) {
                int cc = c + jj - 2;
                vin[jj] = ((unsigned)cc < GW) ? vb[(size_t)(rr * GW + cc) * HD] : 0.f;
            }
            const int jlo = (dr - 2 > 0) ? dr - 2 : 0;
            const int jhi = (dr + 2 < 3) ? dr + 2 : 3;
#pragma unroll
            for (int j = jlo; j <= jhi; j++) {
                const int wi = (dr - j + 2) * 5;
                s[j] += vin[0] * w[wi + 0] + vin[1] * w[wi + 1] + vin[2] * w[wi + 2]
                      + vin[3] * w[wi + 3] + vin[4] * w[wi + 4];
            }
        }
    }

#pragma unroll
    for (int j = 0; j < 4; j++) {
        g_lepe[((size_t)(b * NPOS + (r0 + j) * GW + c)) * CDIM + ch] = s[j];
    }
}

// ---------------------------------------------------------------------------
// Flash attention: tf32 mma, shuffle-free, 256 threads, 256 queries/block,
// 32 rows/warp, split-K over 2 key-halves, double-buffered cp.async.
// grid (NPOS/256 = 9, BH, 2). Unnormalized partials (O, l) -> merge kernel.
// Buffer: ks[128*36] | vt[32*132] | krf[128] | kcf[128]
// ---------------------------------------------------------------------------
#define KS_F 36
#define VT_F 132
#define ABUF 9088
#define AOFF_VT 4608
#define AOFF_KR 8832
#define AOFF_KC 8960
#define NTILE 9               // key tiles per half

__global__ __launch_bounds__(256) void attn_pipe()
{
    extern __shared__ __align__(16) float dyn[];
    const uint32_t sbase = smem_u32(dyn);

    const int tid = threadIdx.x;
    const int lane = tid & 31, wid = tid >> 5;
    const int grp = lane >> 2, t4 = lane & 3;
    const int sg = (grp >> 1) + ((grp & 1) << 2);   // sigma(grp)
    const int bh = blockIdx.y, h = bh & 7;
    const int half = blockIdx.z;
    const int q0 = blockIdx.x * 256;
    const int rowA = q0 + wid * 32 + grp;

    uint32_t qA[2][4][4];
    {
        const float* qb = g_q + (size_t)bh * NPOS * HD;
#pragma unroll
        for (int mi = 0; mi < 2; mi++)
#pragma unroll
            for (int s = 0; s < 4; s++) {
                const float* r0p = qb + (size_t)(rowA + mi * 16) * HD + s * 8;
                const float* r8p = r0p + 8 * HD;
                qA[mi][s][0] = __float_as_uint(r0p[t4]);
                qA[mi][s][1] = __float_as_uint(r8p[t4]);
                qA[mi][s][2] = __float_as_uint(r0p[t4 + 4]);
                qA[mi][s][3] = __float_as_uint(r8p[t4 + 4]);
            }
    }

    float o[2][4][4];
#pragma unroll
    for (int mi = 0; mi < 2; mi++)
#pragma unroll
        for (int i = 0; i < 4; i++)
#pragma unroll
            for (int j = 0; j < 4; j++) o[mi][i][j] = 0.f;
    float lA[2] = {0.f, 0.f}, lB[2] = {0.f, 0.f};

    float qrF[2][2], qcF[2][2];
#pragma unroll
    for (int mi = 0; mi < 2; mi++)
#pragma unroll
        for (int rh = 0; rh < 2; rh++) {
            int qr_ = rowA + mi * 16 + rh * 8;
            int qri = qr_ / GW;
            qrF[mi][rh] = (float)qri;
            qcF[mi][rh] = (float)(qr_ - qri * GW);
        }
    const float decay = logf(1.0f - exp2f(-(1.0f + 0.375f * (float)h)));

    const float* kb = g_k + (size_t)bh * NPOS * HD;
    const float* vtb = g_vt + (size_t)bh * HD * NPOS;

    auto fill = [&](int t, int bb) {
        const uint32_t bu = sbase + (uint32_t)bb * (ABUF * 4);
#pragma unroll
        for (int i = 0; i < 4; i++) {
            int idx = tid + i * 256;
            int row = idx >> 3, c = idx & 7;
            cpa16(bu + (uint32_t)(row * KS_F + c * 4) * 4,
                  kb + ((size_t)t * 128 + row) * HD + c * 4);
        }
#pragma unroll
        for (int i = 0; i < 4; i++) {
            int idx = tid + i * 256;
            int row = idx >> 5, c = idx & 31;
            cpa16(bu + (uint32_t)(AOFF_VT + row * VT_F + c * 4) * 4,
                  vtb + (size_t)row * NPOS + t * 128 + c * 4);
        }
        if (tid < 128) {
            int kk = t * 128 + tid;
            int kr = kk / GW;
            dyn[bb * ABUF + AOFF_KR + tid] = (float)kr;
            dyn[bb * ABUF + AOFF_KC + tid] = (float)(kk - kr * GW);
        }
        asm volatile("cp.async.commit_group;" ::: "memory");
    };

    const int t0 = half * NTILE;
    fill(t0, 0);

    for (int tt = 0; tt < NTILE; tt++) {
        const int bb = tt & 1;
        if (tt < NTILE - 1) {
            fill(t0 + tt + 1, bb ^ 1);
            asm volatile("cp.async.wait_group 1;" ::: "memory");
        } else {
            asm volatile("cp.async.wait_group 0;" ::: "memory");
        }
        __syncthreads();

        const float* ksS = dyn + bb * ABUF;
        const float* vtS = ksS + AOFF_VT;
        const float* krf = ksS + AOFF_KR;
        const float* kcf = ksS + AOFF_KC;

#pragma unroll
        for (int gr = 0; gr < 16; gr++) {
            const float* krow = ksS + (gr * 8 + sg) * KS_F;
            uint32_t kb0[4], kb1[4];
#pragma unroll
            for (int s = 0; s < 4; s++) {
                kb0[s] = __float_as_uint(krow[s * 8 + t4]);
                kb1[s] = __float_as_uint(krow[s * 8 + t4 + 4]);
            }
            float sf[2][4];
#pragma unroll
            for (int mi = 0; mi < 2; mi++) {
                sf[mi][0] = sf[mi][1] = sf[mi][2] = sf[mi][3] = 0.f;
#pragma unroll
                for (int s = 0; s < 4; s++)
                    mma_tf32(sf[mi], qA[mi][s], kb0[s], kb1[s], sf[mi]);
            }
            int col0 = gr * 8 + t4;
            int col1 = col0 + 4;
            float kra = krf[col0], kca = kcf[col0];
            float krb = krf[col1], kcb = kcf[col1];

            uint32_t aP[2][4];
#pragma unroll
            for (int mi = 0; mi < 2; mi++) {
                float p0 = to_tf32f(__expf(fmaf(decay,
                    fabsf(qrF[mi][0] - kra) + fabsf(qcF[mi][0] - kca), sf[mi][0])));
                float p1 = to_tf32f(__expf(fmaf(decay,
                    fabsf(qrF[mi][0] - krb) + fabsf(qcF[mi][0] - kcb), sf[mi][1])));
                float p2 = to_tf32f(__expf(fmaf(decay,
                    fabsf(qrF[mi][1] - kra) + fabsf(qcF[mi][1] - kca), sf[mi][2])));
                float p3 = to_tf32f(__expf(fmaf(decay,
                    fabsf(qrF[mi][1] - krb) + fabsf(qcF[mi][1] - kcb), sf[mi][3])));
                lA[mi] += p0 + p1;
                lB[mi] += p2 + p3;
                aP[mi][0] = __float_as_uint(p0);
                aP[mi][1] = __float_as_uint(p2);
                aP[mi][2] = __float_as_uint(p1);
                aP[mi][3] = __float_as_uint(p3);
            }

#pragma unroll
            for (int nc = 0; nc < 4; nc++) {
                const float* vrow = vtS + (nc * 8 + grp) * VT_F + gr * 8;
                uint32_t b0 = __float_as_uint(vrow[t4]);
                uint32_t b1 = __float_as_uint(vrow[t4 + 4]);
#pragma unroll
                for (int mi = 0; mi < 2; mi++)
                    mma_tf32(o[mi][nc], aP[mi], b0, b1, o[mi][nc]);
            }
        }
        __syncthreads();
    }

#pragma unroll
    for (int mi = 0; mi < 2; mi++) {
        lA[mi] += __shfl_xor_sync(0xFFFFFFFFu, lA[mi], 1);
        lA[mi] += __shfl_xor_sync(0xFFFFFFFFu, lA[mi], 2);
        lB[mi] += __shfl_xor_sync(0xFFFFFFFFu, lB[mi], 1);
        lB[mi] += __shfl_xor_sync(0xFFFFFFFFu, lB[mi], 2);
    }

    // store unnormalized partials
    float* pbase = g_part + (((size_t)(half * BH + bh)) * NPOS) * HD;
#pragma unroll
    for (int mi = 0; mi < 2; mi++) {
        const int r0 = rowA + mi * 16;
        float* p0 = pbase + (size_t)r0 * HD;
        float* p8 = pbase + (size_t)(r0 + 8) * HD;
#pragma unroll
        for (int nc = 0; nc < 4; nc++) {
            int d = nc * 8 + t4 * 2;
            *(float2*)(p0 + d) = make_float2(o[mi][nc][0], o[mi][nc][1]);
            *(float2*)(p8 + d) = make_float2(o[mi][nc][2], o[mi][nc][3]);
        }
        if (t4 == 0) {
            g_partl[(half * BH + bh) * NPOS + r0] = lA[mi];
            g_partl[(half * BH + bh) * NPOS + r0 + 8] = lB[mi];
        }
    }
}

// ---------------------------------------------------------------------------
// Merge split-K halves: g_attn[b][q][h*HD..] = (O0+O1)/(l0+l1)
// ---------------------------------------------------------------------------
__global__ __launch_bounds__(256) void attn_merge()
{
    int t = blockIdx.x * 256 + threadIdx.x;   // BH*NPOS = 36864
    if (t >= BH * NPOS) return;
    int bh = t / NPOS;
    int q = t - bh * NPOS;
    int b = bh >> 3, h = bh & 7;

    float l0 = g_partl[bh * NPOS + q];
    float l1 = g_partl[(BH + bh) * NPOS + q];
    float inv = 1.0f / (l0 + l1);

    const float4* a0 = (const float4*)(g_part + ((size_t)bh * NPOS + q) * HD);
    const float4* a1 = (const float4*)(g_part + ((size_t)(BH + bh) * NPOS + q) * HD);
    float4* o = (float4*)(g_attn + ((size_t)(b * NPOS + q)) * CDIM + h * HD);
#pragma unroll
    for (int i = 0; i < 8; i++) {
        float4 x0 = a0[i], x1 = a1[i];
        o[i] = make_float4((x0.x + x1.x) * inv, (x0.y + x1.y) * inv,
                           (x0.z + x1.z) * inv, (x0.w + x1.w) * inv);
    }
}

// ---------------------------------------------------------------------------
// tf32-mma output GEMM: out = (g_attn + g_lepe) @ Wo + bo
// grid (MTOT/128, CDIM/64)
// ---------------------------------------------------------------------------
__global__ __launch_bounds__(128) void out_mma(
    const float* __restrict__ Wo, const float* __restrict__ bo,
    float* __restrict__ out)
{
    __shared__ __align__(16) float xs[128 * XS];
    __shared__ __align__(16) float ws[32 * WS];

    const int tid = threadIdx.x;
    const int lane = tid & 31, wid = tid >> 5;
    const int grp = lane >> 2, t4 = lane & 3;
    const int mb = blockIdx.x * 128, nb = blockIdx.y * 64;

    float acc[2][8][4];
#pragma unroll
    for (int mi = 0; mi < 2; mi++)
#pragma unroll
        for (int n = 0; n < 8; n++)
#pragma unroll
            for (int j = 0; j < 4; j++) acc[mi][n][j] = 0.f;

    for (int k0 = 0; k0 < CDIM; k0 += 32) {
        __syncthreads();
#pragma unroll
        for (int i = 0; i < 8; i++) {
            int idx = tid + i * 128;
            int row = idx >> 3, c = idx & 7;
            size_t off = (size_t)(mb + row) * CDIM + k0 + c * 4;
            float4 a = *(const float4*)&g_attn[off];
            float4 e = *(const float4*)&g_lepe[off];
            a.x = to_tf32f(a.x + e.x); a.y = to_tf32f(a.y + e.y);
            a.z = to_tf32f(a.z + e.z); a.w = to_tf32f(a.w + e.w);
            *(float4*)(xs + row * XS + c * 4) = a;
        }
#pragma unroll
        for (int i = 0; i < 4; i++) {
            int idx = tid + i * 128;
            int row = idx >> 4, c = idx & 15;
            float4 a = *(const float4*)&Wo[(size_t)(k0 + row) * CDIM + nb + c * 4];
            a.x = to_tf32f(a.x); a.y = to_tf32f(a.y);
            a.z = to_tf32f(a.z); a.w = to_tf32f(a.w);
            *(float4*)(ws + row * WS + c * 4) = a;
        }
        __syncthreads();

#pragma unroll
        for (int ks = 0; ks < 4; ks++) {
            uint32_t bf[8][2];
#pragma unroll
            for (int n = 0; n < 8; n++) {
                bf[n][0] = __float_as_uint(ws[(ks * 8 + t4) * WS + n * 8 + grp]);
                bf[n][1] = __float_as_uint(ws[(ks * 8 + t4 + 4) * WS + n * 8 + grp]);
            }
            uint32_t af[2][4];
#pragma unroll
            for (int mi = 0; mi < 2; mi++) {
                const float* xrow = xs + (wid * 32 + mi * 16 + grp) * XS + ks * 8;
                const float* xrow8 = xrow + 8 * XS;
                af[mi][0] = __float_as_uint(xrow[t4]);
                af[mi][1] = __float_as_uint(xrow8[t4]);
                af[mi][2] = __float_as_uint(xrow[t4 + 4]);
                af[mi][3] = __float_as_uint(xrow8[t4 + 4]);
            }
#pragma unroll
            for (int mi = 0; mi < 2; mi++)
#pragma unroll
                for (int n = 0; n < 8; n++)
                    mma_tf32(acc[mi][n], af[mi], bf[n][0], bf[n][1], acc[mi][n]);
        }
    }

#pragma unroll
    for (int mi = 0; mi < 2; mi++) {
#pragma unroll
        for (int rh = 0; rh < 2; rh++) {
            int row = mb + wid * 32 + mi * 16 + rh * 8 + grp;
#pragma unroll
            for (int n = 0; n < 8; n++) {
                int col = nb + n * 8 + 2 * t4;
                float v0 = acc[mi][n][rh * 2 + 0] + bo[col];
                float v1 = acc[mi][n][rh * 2 + 1] + bo[col + 1];
                *(float2*)&out[(size_t)row * CDIM + col] = make_float2(v0, v1);
            }
        }
    }
}

// ---------------------------------------------------------------------------
extern "C" void kernel_launch(void* const* d_in, const int* in_sizes, int n_in,
                              void* d_out, int out_size)
{
    const float* x      = (const float*)d_in[0];
    const float* Wq     = (const float*)d_in[1];
    const float* bq     = (const float*)d_in[2];
    const float* Wk     = (const float*)d_in[3];
    const float* bk     = (const float*)d_in[4];
    const float* Wv     = (const float*)d_in[5];
    const float* bv     = (const float*)d_in[6];
    const float* lepe_w = (const float*)d_in[7];
    const float* lepe_b = (const float*)d_in[8];
    const float* Wo     = (const float*)d_in[9];
    const float* bo     = (const float*)d_in[10];
    float* out = (float*)d_out;

    setup_tables<<<(NPOS * 16 + 25 * CDIM + 255) / 256, 256>>>(lepe_w);

    dim3 g1(MTOT / 128, CDIM / 64, 3);
    qkv_mma<<<g1, 128>>>(x, Wq, bq, Wk, bk, Wv, bv);

    dim3 gv(NPOS / 32, BH);
    vt_kernel<<<gv, dim3(32, 8)>>>();

    dwconv<<<(MTOT * CDIM / 4) / 256, 256>>>(lepe_b);

    const int attn_smem = 2 * ABUF * 4;   // 72704 B
    cudaFuncSetAttribute(attn_pipe, cudaFuncAttributeMaxDynamicSharedMemorySize, attn_smem);
    dim3 g3(NPOS / 256, BH, 2);
    attn_pipe<<<g3, 256, attn_smem>>>();

    attn_merge<<<(BH * NPOS + 255) / 256, 256>>>();

    dim3 g4(MTOT / 128, CDIM / 64);
    out_mma<<<g4, 128>>>(Wo, bo, out);
}